// round 9
// baseline (speedup 1.0000x reference)
#include <cuda_runtime.h>
#include <cuda_fp16.h>
#include <math_constants.h>
#include <cstdint>

// Problem constants
#define BB   2
#define TT   2048
#define CC   1024
#define HH   16
#define DD   64
#define NTOK (BB * TT)      // 4096
#define QKVN (3 * CC)       // 3072

// ---------------------------------------------------------------------------
// Scratch (no cudaMalloc allowed)
// ---------------------------------------------------------------------------
__device__ __half g_xhi[(size_t)NTOK * CC],  g_xlo[(size_t)NTOK * CC];
__device__ __half g_wahi[(size_t)QKVN * CC];               // [N,K] fp16(W)
__device__ __half g_wphi[(size_t)CC * CC];                 // [N,K] fp16(Wp)
__device__ __half g_qkvhi[(size_t)NTOK * QKVN], g_qkvlo[(size_t)NTOK * QKVN];
__device__ __half g_ahi[(size_t)NTOK * CC],  g_alo[(size_t)NTOK * CC];

// ---------------------------------------------------------------------------
// PTX helpers (plain-sm_103-legal: mma.sync / ldmatrix / cp.async)
// ---------------------------------------------------------------------------
__device__ __forceinline__ uint32_t smem_u32(const void* p) {
    uint32_t a;
    asm("{ .reg .u64 t; cvta.to.shared.u64 t, %1; cvt.u32.u64 %0, t; }"
        : "=r"(a) : "l"(p));
    return a;
}
__device__ __forceinline__ void ldm_x4(uint32_t* r, uint32_t addr) {
    asm volatile("ldmatrix.sync.aligned.m8n8.x4.shared.b16 {%0,%1,%2,%3}, [%4];"
                 : "=r"(r[0]), "=r"(r[1]), "=r"(r[2]), "=r"(r[3]) : "r"(addr));
}
__device__ __forceinline__ void ldm_x4_t(uint32_t* r, uint32_t addr) {
    asm volatile("ldmatrix.sync.aligned.m8n8.x4.trans.shared.b16 {%0,%1,%2,%3}, [%4];"
                 : "=r"(r[0]), "=r"(r[1]), "=r"(r[2]), "=r"(r[3]) : "r"(addr));
}
// fp16 MMA, fp32 accumulate
__device__ __forceinline__ void mma16816(float* d, const uint32_t* a, const uint32_t* b) {
    asm volatile(
        "mma.sync.aligned.m16n8k16.row.col.f32.f16.f16.f32 "
        "{%0,%1,%2,%3}, {%4,%5,%6,%7}, {%8,%9}, {%0,%1,%2,%3};"
        : "+f"(d[0]), "+f"(d[1]), "+f"(d[2]), "+f"(d[3])
        : "r"(a[0]), "r"(a[1]), "r"(a[2]), "r"(a[3]), "r"(b[0]), "r"(b[1]));
}
__device__ __forceinline__ void cp_async16(uint32_t sa, const void* g) {
    asm volatile("cp.async.ca.shared.global [%0], [%1], 16;" :: "r"(sa), "l"(g));
}
#define CP_COMMIT()  asm volatile("cp.async.commit_group;" ::: "memory")
#define CP_WAIT(n)   asm volatile("cp.async.wait_group %0;" :: "n"(n) : "memory")

// pack two fp32 into half2 (lo arg -> low 16 bits)
__device__ __forceinline__ uint32_t pack_h2(float lo, float hi) {
    __half2 h = __floats2half2_rn(lo, hi);
    return *(uint32_t*)&h;
}
__device__ __forceinline__ float h_res(float v) {
    return v - __half2float(__float2half_rn(v));
}
// 16B-granular XOR swizzle on 128-byte rows
__device__ __forceinline__ uint32_t swz(uint32_t base, int row, int bytecol) {
    return base + row * 128 + ((((bytecol >> 4) ^ (row & 7)) << 4));
}

// ---------------------------------------------------------------------------
// fp32 -> (fp16 hi, fp16 lo) elementwise split
// ---------------------------------------------------------------------------
__global__ void split_fp32_kernel(const float* __restrict__ in,
                                  __half* __restrict__ hi,
                                  __half* __restrict__ lo, int n4) {
    int i = blockIdx.x * blockDim.x + threadIdx.x;
    if (i >= n4) return;
    float4 v = ((const float4*)in)[i];
    float vv[4] = {v.x, v.y, v.z, v.w};
    ushort4 sh, sl;
    unsigned short* ph = &sh.x;
    unsigned short* pl = &sl.x;
#pragma unroll
    for (int j = 0; j < 4; j++) {
        __half h = __float2half_rn(vv[j]);
        __half l = __float2half_rn(vv[j] - __half2float(h));
        ph[j] = __half_as_ushort(h);
        pl[j] = __half_as_ushort(l);
    }
    ((ushort4*)hi)[i] = sh;
    ((ushort4*)lo)[i] = sl;
}

// ---------------------------------------------------------------------------
// fp32 [K,N] -> transposed fp16 [N,K]
// ---------------------------------------------------------------------------
__global__ void split_transpose_kernel(const float* __restrict__ in,
                                       __half* __restrict__ hi,
                                       int K, int N) {
    __shared__ float tile[32][33];
    int bx = blockIdx.x * 32;
    int by = blockIdx.y * 32;
    int tx = threadIdx.x, ty = threadIdx.y;
#pragma unroll
    for (int i = 0; i < 32; i += 8)
        tile[ty + i][tx] = in[(size_t)(by + ty + i) * N + bx + tx];
    __syncthreads();
#pragma unroll
    for (int i = 0; i < 32; i += 8) {
        float v = tile[tx][ty + i];
        hi[(size_t)(bx + ty + i) * K + by + tx] = __float2half_rn(v);
    }
}

// ---------------------------------------------------------------------------
// Split-fp16 2-term mma.sync GEMM: C[M,N] = (Ahi+Alo)[M,K] @ Bhi[N,K]^T + bias
// BK=64, XOR-swizzled 128B rows, 2-stage cp.async, 2 CTAs/SM.
// ---------------------------------------------------------------------------
#define GTILE  16384                 // 128 rows x 128 bytes (64 fp16)
#define GSTAGE (3 * GTILE)           // Ahi|Alo|Bhi = 48KB
#define GEMM_SMEM (2 * GSTAGE + 128)

__global__ __launch_bounds__(256, 2) void gemm_mma_kernel(
    const __half* __restrict__ Ahi, const __half* __restrict__ Alo,
    const __half* __restrict__ Bhi,
    const float* __restrict__ bias, float* __restrict__ Cf,
    __half* __restrict__ Chi, __half* __restrict__ Clo,
    int M, int N, int K)
{
    extern __shared__ char dsm[];
    const uint32_t dynb = smem_u32(dsm);
    const uint32_t sb_u = (dynb + 127) & ~127u;

    const int tid  = threadIdx.x;
    const int wid  = tid >> 5;
    const int lane = tid & 31;
    const int wm   = wid >> 2;
    const int wn   = wid & 3;
    const int m0 = blockIdx.y * 128;
    const int n0 = blockIdx.x * 128;

    const int lrow = lane & 15;
    const int lc16 = (lane >> 4) << 4;   // +16B for lanes >= 16

    float acc[4][4][4];
#pragma unroll
    for (int a = 0; a < 4; a++)
#pragma unroll
        for (int b = 0; b < 4; b++)
#pragma unroll
            for (int c = 0; c < 4; c++) acc[a][b][c] = 0.0f;

    const int nCh = K >> 6;   // BK = 64

    auto load_stage = [&](int c, int s) {
        const int kc = c << 6;
#pragma unroll
        for (int it = 0; it < 12; it++) {
            int i    = it * 256 + tid;      // 0..3071
            int tile = i >> 10;             // 0..2 : Ahi, Alo, Bhi
            int w    = i & 1023;
            int row  = w >> 3;              // 0..127
            int slot = w & 7;               // 16B slots (8 per row)
            const __half* gp;
            if      (tile == 0) gp = Ahi + (size_t)(m0 + row) * K + kc + slot * 8;
            else if (tile == 1) gp = Alo + (size_t)(m0 + row) * K + kc + slot * 8;
            else                gp = Bhi + (size_t)(n0 + row) * K + kc + slot * 8;
            cp_async16(swz(sb_u + s * GSTAGE + tile * GTILE, row, slot * 16), gp);
        }
        CP_COMMIT();
    };

    auto compute = [&](int s) {
        const uint32_t aHi = sb_u + s * GSTAGE;
        const uint32_t aLo = aHi + GTILE;
        const uint32_t bHi = aHi + 2 * GTILE;
#pragma unroll
        for (int ks = 0; ks < 4; ks++) {
            const int kb = ks * 32 + lc16;
            uint32_t bhi[4][2];
#pragma unroll
            for (int bg = 0; bg < 2; bg++) {
                int row = wn * 32 + bg * 16 + lrow;
                uint32_t t[4];
                ldm_x4(t, swz(bHi, row, kb));
                bhi[bg * 2][0] = t[0]; bhi[bg * 2 + 1][0] = t[1];
                bhi[bg * 2][1] = t[2]; bhi[bg * 2 + 1][1] = t[3];
            }
#pragma unroll
            for (int mh = 0; mh < 2; mh++) {
                uint32_t ahi[2][4], alo[2][4];
#pragma unroll
                for (int mi = 0; mi < 2; mi++) {
                    int row = wm * 64 + (mh * 2 + mi) * 16 + lrow;
                    ldm_x4(ahi[mi], swz(aHi, row, kb));
                    ldm_x4(alo[mi], swz(aLo, row, kb));
                }
#pragma unroll
                for (int mi = 0; mi < 2; mi++)
#pragma unroll
                    for (int nf = 0; nf < 4; nf++)
                        mma16816(acc[mh * 2 + mi][nf], ahi[mi], bhi[nf]);
#pragma unroll
                for (int mi = 0; mi < 2; mi++)
#pragma unroll
                    for (int nf = 0; nf < 4; nf++)
                        mma16816(acc[mh * 2 + mi][nf], alo[mi], bhi[nf]);
            }
        }
    };

    // 2-stage pipeline
    load_stage(0, 0);
    for (int c = 0; c < nCh; c++) {
        const int s = c & 1;
        __syncthreads();
        if (c + 1 < nCh) {
            load_stage(c + 1, s ^ 1);
            CP_WAIT(1);
        } else {
            CP_WAIT(0);
        }
        __syncthreads();
        compute(s);
    }

    const int g = lane >> 2;
    const int t2 = (lane & 3) * 2;
#pragma unroll
    for (int mf = 0; mf < 4; mf++) {
#pragma unroll
        for (int nf = 0; nf < 4; nf++) {
            int col = n0 + wn * 32 + nf * 8 + t2;
            float2 bv = *(const float2*)(bias + col);
            int r0 = m0 + wm * 64 + mf * 16 + g;
            float v0 = acc[mf][nf][0] + bv.x, v1 = acc[mf][nf][1] + bv.y;
            float v2 = acc[mf][nf][2] + bv.x, v3 = acc[mf][nf][3] + bv.y;
            if (Chi) {
                size_t i0 = ((size_t)r0 * N + col) >> 1;
                size_t i1 = ((size_t)(r0 + 8) * N + col) >> 1;
                ((uint32_t*)Chi)[i0] = pack_h2(v0, v1);
                ((uint32_t*)Clo)[i0] = pack_h2(h_res(v0), h_res(v1));
                ((uint32_t*)Chi)[i1] = pack_h2(v2, v3);
                ((uint32_t*)Clo)[i1] = pack_h2(h_res(v2), h_res(v3));
            } else {
                float2 o0 = {v0, v1}, o1 = {v2, v3};
                *(float2*)(Cf + (size_t)r0 * N + col)       = o0;
                *(float2*)(Cf + (size_t)(r0 + 8) * N + col) = o1;
            }
        }
    }
}

// ---------------------------------------------------------------------------
// Tensor-core flash attention (causal), fp16 2-term.
// K-tile = 64 keys/iteration -> S registers halved -> 2 CTAs/SM.
// ---------------------------------------------------------------------------
#define FK_TILE 8192                        // 64 rows x 128B (64 fp16)
#define F_STAGE (2 * FK_TILE)               // Khi|Vhi = 16KB
#define FLASH_SMEM (2 * F_STAGE + 128)

__global__ __launch_bounds__(256, 2) void flash_mma_kernel(
    const __half* __restrict__ qkvhi,
    const __half* __restrict__ qkvlo,
    __half* __restrict__ ohi,
    __half* __restrict__ olo)
{
    extern __shared__ char dsm[];
    const uint32_t dynb = smem_u32(dsm);
    const uint32_t stgS = (dynb + 127) & ~127u;

    const int tid  = threadIdx.x;
    const int wid  = tid >> 5;
    const int lane = tid & 31;
    const int lrow = lane & 15;
    const int lc16 = (lane >> 4) << 4;
    const int g    = lane >> 2;
    const int t2   = (lane & 3) * 2;

    const int b  = blockIdx.y >> 4;
    const int h  = blockIdx.y & 15;
    const int qt = (int)gridDim.x - 1 - (int)blockIdx.x;

    const size_t rowQ = (size_t)(b * TT + qt * 128);
    const int qcol = h * DD;
    const int kcol = CC + h * DD;
    const int vcol = 2 * CC + h * DD;

    const int nkt = 2 * qt + 2;   // 64-key tiles

    auto load_stage = [&](int kt, int s) {
        const size_t rowK = (size_t)(b * TT + kt * 64);
        const uint32_t st = stgS + s * F_STAGE;
#pragma unroll
        for (int it = 0; it < 4; it++) {
            int i = it * 256 + tid;      // 0..1023
            int t = i >> 9;              // 0 = Khi, 1 = Vhi
            int w = i & 511;
            int r = w >> 3, c = w & 7;
            int colb = t ? vcol : kcol;
            cp_async16(swz(st + t * FK_TILE, r, c * 16),
                       qkvhi + (rowK + r) * QKVN + colb + c * 8);
        }
        CP_COMMIT();
    };

    load_stage(0, 0);

    // ---- Q hi/lo fragments direct from gmem ----
    uint32_t qh[4][4], ql[4][4];
    {
        const size_t r0 = rowQ + wid * 16 + g;
        const size_t r1 = r0 + 8;
        const __half* ph0 = qkvhi + r0 * QKVN + qcol;
        const __half* ph1 = qkvhi + r1 * QKVN + qcol;
        const __half* pl0 = qkvlo + r0 * QKVN + qcol;
        const __half* pl1 = qkvlo + r1 * QKVN + qcol;
#pragma unroll
        for (int ks = 0; ks < 4; ks++) {
            int c0 = t2 + ks * 16;
            qh[ks][0] = *(const uint32_t*)(ph0 + c0);
            qh[ks][1] = *(const uint32_t*)(ph1 + c0);
            qh[ks][2] = *(const uint32_t*)(ph0 + c0 + 8);
            qh[ks][3] = *(const uint32_t*)(ph1 + c0 + 8);
            ql[ks][0] = *(const uint32_t*)(pl0 + c0);
            ql[ks][1] = *(const uint32_t*)(pl1 + c0);
            ql[ks][2] = *(const uint32_t*)(pl0 + c0 + 8);
            ql[ks][3] = *(const uint32_t*)(pl1 + c0 + 8);
        }
    }

    float o[8][4];
#pragma unroll
    for (int nd = 0; nd < 8; nd++)
#pragma unroll
        for (int c = 0; c < 4; c++) o[nd][c] = 0.0f;
    float m0 = -CUDART_INF_F, m1 = -CUDART_INF_F;
    float l0 = 0.0f, l1 = 0.0f;

    // q rows handled by this thread (local within the 128-row tile)
    const int rl0 = wid * 16 + g;
    const int rl1 = rl0 + 8;

    for (int kt = 0; kt < nkt; kt++) {
        const int s = kt & 1;
        if (kt + 1 < nkt) {
            load_stage(kt + 1, s ^ 1);
            CP_WAIT(1);
        } else {
            CP_WAIT(0);
        }
        __syncthreads();

        const uint32_t khiS = stgS + s * F_STAGE;
        const uint32_t vhiS = khiS + FK_TILE;

        // ---- S = Q K^T (2-term), 64 cols ----
        float sc[8][4];
#pragma unroll
        for (int nf = 0; nf < 8; nf++)
#pragma unroll
            for (int c = 0; c < 4; c++) sc[nf][c] = 0.0f;

#pragma unroll
        for (int ks = 0; ks < 4; ks++) {
            const int kb = ks * 32 + lc16;
            uint32_t tk[4][4];
#pragma unroll
            for (int kf = 0; kf < 4; kf++)
                ldm_x4(tk[kf], swz(khiS, kf * 16 + lrow, kb));
#pragma unroll
            for (int kf = 0; kf < 4; kf++) {
                uint32_t b0[2] = {tk[kf][0], tk[kf][2]};
                uint32_t b1[2] = {tk[kf][1], tk[kf][3]};
                mma16816(sc[2 * kf],     qh[ks], b0);
                mma16816(sc[2 * kf + 1], qh[ks], b1);
            }
#pragma unroll
            for (int kf = 0; kf < 4; kf++) {
                uint32_t b0[2] = {tk[kf][0], tk[kf][2]};
                uint32_t b1[2] = {tk[kf][1], tk[kf][3]};
                mma16816(sc[2 * kf],     ql[ks], b0);
                mma16816(sc[2 * kf + 1], ql[ks], b1);
            }
        }

        // ---- scale + causal mask + online softmax ----
        const float scale = 0.125f;
        const bool diag = (kt >= 2 * qt);   // only the last 2 k-tiles intersect the diagonal
        float rm0 = -CUDART_INF_F, rm1 = -CUDART_INF_F;
#pragma unroll
        for (int nf = 0; nf < 8; nf++) {
            float c0 = sc[nf][0] * scale, c1 = sc[nf][1] * scale;
            float c2 = sc[nf][2] * scale, c3 = sc[nf][3] * scale;
            if (diag) {
                int col = kt * 64 + nf * 8 + t2 - qt * 128;  // col relative to tile rows
                if (col     > rl0) c0 = -1e30f;
                if (col + 1 > rl0) c1 = -1e30f;
                if (col     > rl1) c2 = -1e30f;
                if (col + 1 > rl1) c3 = -1e30f;
            }
            sc[nf][0] = c0; sc[nf][1] = c1; sc[nf][2] = c2; sc[nf][3] = c3;
            rm0 = fmaxf(rm0, fmaxf(c0, c1));
            rm1 = fmaxf(rm1, fmaxf(c2, c3));
        }
        rm0 = fmaxf(rm0, __shfl_xor_sync(0xffffffffu, rm0, 1));
        rm0 = fmaxf(rm0, __shfl_xor_sync(0xffffffffu, rm0, 2));
        rm1 = fmaxf(rm1, __shfl_xor_sync(0xffffffffu, rm1, 1));
        rm1 = fmaxf(rm1, __shfl_xor_sync(0xffffffffu, rm1, 2));

        const float mn0 = fmaxf(m0, rm0), mn1 = fmaxf(m1, rm1);
        const float a0 = __expf(m0 - mn0), a1 = __expf(m1 - mn1);
        float rs0 = 0.0f, rs1 = 0.0f;
#pragma unroll
        for (int nf = 0; nf < 8; nf++) {
            float p0 = __expf(sc[nf][0] - mn0);
            float p1 = __expf(sc[nf][1] - mn0);
            float p2 = __expf(sc[nf][2] - mn1);
            float p3 = __expf(sc[nf][3] - mn1);
            sc[nf][0] = p0; sc[nf][1] = p1; sc[nf][2] = p2; sc[nf][3] = p3;
            rs0 += p0 + p1;
            rs1 += p2 + p3;
        }
        rs0 += __shfl_xor_sync(0xffffffffu, rs0, 1);
        rs0 += __shfl_xor_sync(0xffffffffu, rs0, 2);
        rs1 += __shfl_xor_sync(0xffffffffu, rs1, 1);
        rs1 += __shfl_xor_sync(0xffffffffu, rs1, 2);
        l0 = l0 * a0 + rs0;
        l1 = l1 * a1 + rs1;
        m0 = mn0;
        m1 = mn1;
#pragma unroll
        for (int nd = 0; nd < 8; nd++) {
            o[nd][0] *= a0; o[nd][1] *= a0;
            o[nd][2] *= a1; o[nd][3] *= a1;
        }

        // ---- O += P V (2-term) ----
#pragma unroll
        for (int kk = 0; kk < 4; kk++) {
            float* p0 = sc[2 * kk];
            float* p1 = sc[2 * kk + 1];
            uint32_t phi[4], plo[4];
            phi[0] = pack_h2(p0[0], p0[1]);
            phi[1] = pack_h2(p0[2], p0[3]);
            phi[2] = pack_h2(p1[0], p1[1]);
            phi[3] = pack_h2(p1[2], p1[3]);
            plo[0] = pack_h2(h_res(p0[0]), h_res(p0[1]));
            plo[1] = pack_h2(h_res(p0[2]), h_res(p0[3]));
            plo[2] = pack_h2(h_res(p1[0]), h_res(p1[1]));
            plo[3] = pack_h2(h_res(p1[2]), h_res(p1[3]));

            uint32_t tv[4][4];
#pragma unroll
            for (int df = 0; df < 4; df++)
                ldm_x4_t(tv[df], swz(vhiS, kk * 16 + lrow, df * 32 + lc16));
#pragma unroll
            for (int df = 0; df < 4; df++) {
                uint32_t v0[2] = {tv[df][0], tv[df][1]};
                uint32_t v1[2] = {tv[df][2], tv[df][3]};
                mma16816(o[2 * df],     phi, v0);
                mma16816(o[2 * df + 1], phi, v1);
            }
#pragma unroll
            for (int df = 0; df < 4; df++) {
                uint32_t v0[2] = {tv[df][0], tv[df][1]};
                uint32_t v1[2] = {tv[df][2], tv[df][3]};
                mma16816(o[2 * df],     plo, v0);
                mma16816(o[2 * df + 1], plo, v1);
            }
        }
        __syncthreads();   // all warps done with stage s before overwrite
    }

    // ---- epilogue: normalize, split to fp16 hi/lo ----
    const float inv0 = 1.0f / l0;
    const float inv1 = 1.0f / l1;
    const size_t r0 = rowQ + rl0;
    const size_t r1 = rowQ + rl1;
#pragma unroll
    for (int nd = 0; nd < 8; nd++) {
        int col = h * DD + nd * 8 + t2;
        float v0 = o[nd][0] * inv0, v1 = o[nd][1] * inv0;
        float v2 = o[nd][2] * inv1, v3 = o[nd][3] * inv1;
        size_t i0 = (r0 * CC + col) >> 1;
        size_t i1 = (r1 * CC + col) >> 1;
        ((uint32_t*)ohi)[i0] = pack_h2(v0, v1);
        ((uint32_t*)olo)[i0] = pack_h2(h_res(v0), h_res(v1));
        ((uint32_t*)ohi)[i1] = pack_h2(v2, v3);
        ((uint32_t*)olo)[i1] = pack_h2(h_res(v2), h_res(v3));
    }
}

// ---------------------------------------------------------------------------
// Launch
// ---------------------------------------------------------------------------
extern "C" void kernel_launch(void* const* d_in, const int* in_sizes, int n_in,
                              void* d_out, int out_size)
{
    (void)in_sizes; (void)n_in; (void)out_size;
    const float* x      = (const float*)d_in[0];
    const float* w_attn = (const float*)d_in[1];
    const float* b_attn = (const float*)d_in[2];
    const float* w_proj = (const float*)d_in[3];
    const float* b_proj = (const float*)d_in[4];
    float* out = (float*)d_out;

    __half *xhi, *xlo, *wahi, *wphi;
    __half *qkvhi, *qkvlo, *ahi, *alo;
    cudaGetSymbolAddress((void**)&xhi,   g_xhi);
    cudaGetSymbolAddress((void**)&xlo,   g_xlo);
    cudaGetSymbolAddress((void**)&wahi,  g_wahi);
    cudaGetSymbolAddress((void**)&wphi,  g_wphi);
    cudaGetSymbolAddress((void**)&qkvhi, g_qkvhi);
    cudaGetSymbolAddress((void**)&qkvlo, g_qkvlo);
    cudaGetSymbolAddress((void**)&ahi,   g_ahi);
    cudaGetSymbolAddress((void**)&alo,   g_alo);

    cudaFuncSetAttribute(gemm_mma_kernel,
                         cudaFuncAttributeMaxDynamicSharedMemorySize, GEMM_SMEM);
    cudaFuncSetAttribute(flash_mma_kernel,
                         cudaFuncAttributeMaxDynamicSharedMemorySize, FLASH_SMEM);

    // 1) split x -> fp16 hi/lo
    {
        int n4 = NTOK * CC / 4;
        split_fp32_kernel<<<(n4 + 255) / 256, 256>>>(x, xhi, xlo, n4);
    }
    // 2) transpose weights -> [N,K] fp16
    {
        dim3 blk(32, 8);
        split_transpose_kernel<<<dim3(QKVN / 32, CC / 32), blk>>>(w_attn, wahi, CC, QKVN);
        split_transpose_kernel<<<dim3(CC / 32, CC / 32), blk>>>(w_proj, wphi, CC, CC);
    }
    // 3) QKV GEMM -> split fp16 hi/lo qkv
    {
        dim3 grid(QKVN / 128, NTOK / 128);
        gemm_mma_kernel<<<grid, 256, GEMM_SMEM>>>(xhi, xlo, wahi,
                                                  b_attn, nullptr, qkvhi, qkvlo,
                                                  NTOK, QKVN, CC);
    }
    // 4) tensor-core flash attention -> split fp16 hi/lo y
    {
        dim3 grid(TT / 128, BB * HH);
        flash_mma_kernel<<<grid, 256, FLASH_SMEM>>>(qkvhi, qkvlo, ahi, alo);
    }
    // 5) proj GEMM -> fp32 out
    {
        dim3 grid(CC / 128, NTOK / 128);
        gemm_mma_kernel<<<grid, 256, GEMM_SMEM>>>(ahi, alo, wphi,
                                                  b_proj, out, nullptr, nullptr,
                                                  NTOK, CC, CC);
    }
}

// round 10
// speedup vs baseline: 1.0669x; 1.0669x over previous
#include <cuda_runtime.h>
#include <cuda_fp16.h>
#include <math_constants.h>
#include <cstdint>

// Problem constants
#define BB   2
#define TT   2048
#define CC   1024
#define HH   16
#define DD   64
#define NTOK (BB * TT)      // 4096
#define QKVN (3 * CC)       // 3072

// ---------------------------------------------------------------------------
// Scratch (no cudaMalloc allowed)
// ---------------------------------------------------------------------------
__device__ __half g_xhi[(size_t)NTOK * CC],  g_xlo[(size_t)NTOK * CC];
__device__ __half g_wahi[(size_t)QKVN * CC];               // [N,K] fp16(W)
__device__ __half g_wphi[(size_t)CC * CC];                 // [N,K] fp16(Wp)
__device__ __half g_qkvhi[(size_t)NTOK * QKVN], g_qkvlo[(size_t)NTOK * QKVN];
__device__ __half g_ahi[(size_t)NTOK * CC],  g_alo[(size_t)NTOK * CC];

// ---------------------------------------------------------------------------
// PTX helpers (plain-sm_103-legal: mma.sync / ldmatrix / cp.async)
// ---------------------------------------------------------------------------
__device__ __forceinline__ uint32_t smem_u32(const void* p) {
    uint32_t a;
    asm("{ .reg .u64 t; cvta.to.shared.u64 t, %1; cvt.u32.u64 %0, t; }"
        : "=r"(a) : "l"(p));
    return a;
}
__device__ __forceinline__ void ldm_x4(uint32_t* r, uint32_t addr) {
    asm volatile("ldmatrix.sync.aligned.m8n8.x4.shared.b16 {%0,%1,%2,%3}, [%4];"
                 : "=r"(r[0]), "=r"(r[1]), "=r"(r[2]), "=r"(r[3]) : "r"(addr));
}
__device__ __forceinline__ void ldm_x4_t(uint32_t* r, uint32_t addr) {
    asm volatile("ldmatrix.sync.aligned.m8n8.x4.trans.shared.b16 {%0,%1,%2,%3}, [%4];"
                 : "=r"(r[0]), "=r"(r[1]), "=r"(r[2]), "=r"(r[3]) : "r"(addr));
}
// fp16 MMA, fp32 accumulate
__device__ __forceinline__ void mma16816(float* d, const uint32_t* a, const uint32_t* b) {
    asm volatile(
        "mma.sync.aligned.m16n8k16.row.col.f32.f16.f16.f32 "
        "{%0,%1,%2,%3}, {%4,%5,%6,%7}, {%8,%9}, {%0,%1,%2,%3};"
        : "+f"(d[0]), "+f"(d[1]), "+f"(d[2]), "+f"(d[3])
        : "r"(a[0]), "r"(a[1]), "r"(a[2]), "r"(a[3]), "r"(b[0]), "r"(b[1]));
}
__device__ __forceinline__ void cp_async16(uint32_t sa, const void* g) {
    asm volatile("cp.async.ca.shared.global [%0], [%1], 16;" :: "r"(sa), "l"(g));
}
#define CP_COMMIT()  asm volatile("cp.async.commit_group;" ::: "memory")
#define CP_WAIT(n)   asm volatile("cp.async.wait_group %0;" :: "n"(n) : "memory")

// pack two fp32 into half2 (lo arg -> low 16 bits)
__device__ __forceinline__ uint32_t pack_h2(float lo, float hi) {
    __half2 h = __floats2half2_rn(lo, hi);
    return *(uint32_t*)&h;
}
__device__ __forceinline__ float h_res(float v) {
    return v - __half2float(__float2half_rn(v));
}
// 16B-granular XOR swizzle on 128-byte rows
__device__ __forceinline__ uint32_t swz(uint32_t base, int row, int bytecol) {
    return base + row * 128 + ((((bytecol >> 4) ^ (row & 7)) << 4));
}

// ---------------------------------------------------------------------------
// fp32 -> (fp16 hi, fp16 lo) elementwise split
// ---------------------------------------------------------------------------
__global__ void split_fp32_kernel(const float* __restrict__ in,
                                  __half* __restrict__ hi,
                                  __half* __restrict__ lo, int n4) {
    int i = blockIdx.x * blockDim.x + threadIdx.x;
    if (i >= n4) return;
    float4 v = ((const float4*)in)[i];
    float vv[4] = {v.x, v.y, v.z, v.w};
    ushort4 sh, sl;
    unsigned short* ph = &sh.x;
    unsigned short* pl = &sl.x;
#pragma unroll
    for (int j = 0; j < 4; j++) {
        __half h = __float2half_rn(vv[j]);
        __half l = __float2half_rn(vv[j] - __half2float(h));
        ph[j] = __half_as_ushort(h);
        pl[j] = __half_as_ushort(l);
    }
    ((ushort4*)hi)[i] = sh;
    ((ushort4*)lo)[i] = sl;
}

// ---------------------------------------------------------------------------
// fp32 [K,N] -> transposed fp16 [N,K]
// ---------------------------------------------------------------------------
__global__ void split_transpose_kernel(const float* __restrict__ in,
                                       __half* __restrict__ hi,
                                       int K, int N) {
    __shared__ float tile[32][33];
    int bx = blockIdx.x * 32;
    int by = blockIdx.y * 32;
    int tx = threadIdx.x, ty = threadIdx.y;
#pragma unroll
    for (int i = 0; i < 32; i += 8)
        tile[ty + i][tx] = in[(size_t)(by + ty + i) * N + bx + tx];
    __syncthreads();
#pragma unroll
    for (int i = 0; i < 32; i += 8) {
        float v = tile[tx][ty + i];
        hi[(size_t)(bx + ty + i) * K + by + tx] = __float2half_rn(v);
    }
}

// ---------------------------------------------------------------------------
// Split-fp16 2-term mma.sync GEMM: C[M,N] = (Ahi+Alo)[M,K] @ Bhi[N,K]^T + bias
// BK=64, XOR-swizzled 128B rows, 2-stage cp.async, 2 CTAs/SM. (R9 version)
// ---------------------------------------------------------------------------
#define GTILE  16384                 // 128 rows x 128 bytes (64 fp16)
#define GSTAGE (3 * GTILE)           // Ahi|Alo|Bhi = 48KB
#define GEMM_SMEM (2 * GSTAGE + 128)

__global__ __launch_bounds__(256, 2) void gemm_mma_kernel(
    const __half* __restrict__ Ahi, const __half* __restrict__ Alo,
    const __half* __restrict__ Bhi,
    const float* __restrict__ bias, float* __restrict__ Cf,
    __half* __restrict__ Chi, __half* __restrict__ Clo,
    int M, int N, int K)
{
    extern __shared__ char dsm[];
    const uint32_t dynb = smem_u32(dsm);
    const uint32_t sb_u = (dynb + 127) & ~127u;

    const int tid  = threadIdx.x;
    const int wid  = tid >> 5;
    const int lane = tid & 31;
    const int wm   = wid >> 2;
    const int wn   = wid & 3;
    const int m0 = blockIdx.y * 128;
    const int n0 = blockIdx.x * 128;

    const int lrow = lane & 15;
    const int lc16 = (lane >> 4) << 4;   // +16B for lanes >= 16

    float acc[4][4][4];
#pragma unroll
    for (int a = 0; a < 4; a++)
#pragma unroll
        for (int b = 0; b < 4; b++)
#pragma unroll
            for (int c = 0; c < 4; c++) acc[a][b][c] = 0.0f;

    const int nCh = K >> 6;   // BK = 64

    auto load_stage = [&](int c, int s) {
        const int kc = c << 6;
#pragma unroll
        for (int it = 0; it < 12; it++) {
            int i    = it * 256 + tid;      // 0..3071
            int tile = i >> 10;             // 0..2 : Ahi, Alo, Bhi
            int w    = i & 1023;
            int row  = w >> 3;              // 0..127
            int slot = w & 7;               // 16B slots (8 per row)
            const __half* gp;
            if      (tile == 0) gp = Ahi + (size_t)(m0 + row) * K + kc + slot * 8;
            else if (tile == 1) gp = Alo + (size_t)(m0 + row) * K + kc + slot * 8;
            else                gp = Bhi + (size_t)(n0 + row) * K + kc + slot * 8;
            cp_async16(swz(sb_u + s * GSTAGE + tile * GTILE, row, slot * 16), gp);
        }
        CP_COMMIT();
    };

    auto compute = [&](int s) {
        const uint32_t aHi = sb_u + s * GSTAGE;
        const uint32_t aLo = aHi + GTILE;
        const uint32_t bHi = aHi + 2 * GTILE;
#pragma unroll
        for (int ks = 0; ks < 4; ks++) {
            const int kb = ks * 32 + lc16;
            uint32_t bhi[4][2];
#pragma unroll
            for (int bg = 0; bg < 2; bg++) {
                int row = wn * 32 + bg * 16 + lrow;
                uint32_t t[4];
                ldm_x4(t, swz(bHi, row, kb));
                bhi[bg * 2][0] = t[0]; bhi[bg * 2 + 1][0] = t[1];
                bhi[bg * 2][1] = t[2]; bhi[bg * 2 + 1][1] = t[3];
            }
#pragma unroll
            for (int mh = 0; mh < 2; mh++) {
                uint32_t ahi[2][4], alo[2][4];
#pragma unroll
                for (int mi = 0; mi < 2; mi++) {
                    int row = wm * 64 + (mh * 2 + mi) * 16 + lrow;
                    ldm_x4(ahi[mi], swz(aHi, row, kb));
                    ldm_x4(alo[mi], swz(aLo, row, kb));
                }
#pragma unroll
                for (int mi = 0; mi < 2; mi++)
#pragma unroll
                    for (int nf = 0; nf < 4; nf++)
                        mma16816(acc[mh * 2 + mi][nf], ahi[mi], bhi[nf]);
#pragma unroll
                for (int mi = 0; mi < 2; mi++)
#pragma unroll
                    for (int nf = 0; nf < 4; nf++)
                        mma16816(acc[mh * 2 + mi][nf], alo[mi], bhi[nf]);
            }
        }
    };

    // 2-stage pipeline
    load_stage(0, 0);
    for (int c = 0; c < nCh; c++) {
        const int s = c & 1;
        __syncthreads();
        if (c + 1 < nCh) {
            load_stage(c + 1, s ^ 1);
            CP_WAIT(1);
        } else {
            CP_WAIT(0);
        }
        __syncthreads();
        compute(s);
    }

    const int g = lane >> 2;
    const int t2 = (lane & 3) * 2;
#pragma unroll
    for (int mf = 0; mf < 4; mf++) {
#pragma unroll
        for (int nf = 0; nf < 4; nf++) {
            int col = n0 + wn * 32 + nf * 8 + t2;
            float2 bv = *(const float2*)(bias + col);
            int r0 = m0 + wm * 64 + mf * 16 + g;
            float v0 = acc[mf][nf][0] + bv.x, v1 = acc[mf][nf][1] + bv.y;
            float v2 = acc[mf][nf][2] + bv.x, v3 = acc[mf][nf][3] + bv.y;
            if (Chi) {
                size_t i0 = ((size_t)r0 * N + col) >> 1;
                size_t i1 = ((size_t)(r0 + 8) * N + col) >> 1;
                ((uint32_t*)Chi)[i0] = pack_h2(v0, v1);
                ((uint32_t*)Clo)[i0] = pack_h2(h_res(v0), h_res(v1));
                ((uint32_t*)Chi)[i1] = pack_h2(v2, v3);
                ((uint32_t*)Clo)[i1] = pack_h2(h_res(v2), h_res(v3));
            } else {
                float2 o0 = {v0, v1}, o1 = {v2, v3};
                *(float2*)(Cf + (size_t)r0 * N + col)       = o0;
                *(float2*)(Cf + (size_t)(r0 + 8) * N + col) = o1;
            }
        }
    }
}

// ---------------------------------------------------------------------------
// Tensor-core flash attention (causal), fp16 2-term (R8 version):
//   S = (qhi+qlo) . khi ;  O = (phi+plo) . vhi
// Q hi/lo fragments in registers; K/V (hi only, 128-key tiles) 2-stage pipeline.
// ---------------------------------------------------------------------------
#define FT_TILE 16384                       // 128 x 64 fp16
#define FT_STAGE (2 * FT_TILE)              // Khi|Vhi = 32KB
#define FLASH_SMEM (2 * FT_STAGE + 128)

__global__ __launch_bounds__(256, 1) void flash_mma_kernel(
    const __half* __restrict__ qkvhi,
    const __half* __restrict__ qkvlo,
    __half* __restrict__ ohi,
    __half* __restrict__ olo)
{
    extern __shared__ char dsm[];
    const uint32_t dynb = smem_u32(dsm);
    const uint32_t stgS = (dynb + 127) & ~127u;

    const int tid  = threadIdx.x;
    const int wid  = tid >> 5;
    const int lane = tid & 31;
    const int lrow = lane & 15;
    const int lc16 = (lane >> 4) << 4;
    const int g    = lane >> 2;
    const int t2   = (lane & 3) * 2;

    const int b  = blockIdx.y >> 4;
    const int h  = blockIdx.y & 15;
    const int qt = (int)gridDim.x - 1 - (int)blockIdx.x;

    const size_t rowQ = (size_t)(b * TT + qt * 128);
    const int qcol = h * DD;
    const int kcol = CC + h * DD;
    const int vcol = 2 * CC + h * DD;

    auto load_stage = [&](int kt, int s) {
        const size_t rowK = (size_t)(b * TT + kt * 128);
        const uint32_t st = stgS + s * FT_STAGE;
#pragma unroll
        for (int it = 0; it < 8; it++) {
            int i = it * 256 + tid;      // 0..2047
            int t = i >> 10;             // 0 = Khi, 1 = Vhi
            int w = i & 1023;
            int r = w >> 3, c = w & 7;
            int colb = t ? vcol : kcol;
            cp_async16(swz(st + t * FT_TILE, r, c * 16),
                       qkvhi + (rowK + r) * QKVN + colb + c * 8);
        }
        CP_COMMIT();
    };

    load_stage(0, 0);

    // ---- Q hi/lo fragments direct from gmem ----
    uint32_t qh[4][4], ql[4][4];
    {
        const size_t r0 = rowQ + wid * 16 + g;
        const size_t r1 = r0 + 8;
        const __half* ph0 = qkvhi + r0 * QKVN + qcol;
        const __half* ph1 = qkvhi + r1 * QKVN + qcol;
        const __half* pl0 = qkvlo + r0 * QKVN + qcol;
        const __half* pl1 = qkvlo + r1 * QKVN + qcol;
#pragma unroll
        for (int ks = 0; ks < 4; ks++) {
            int c0 = t2 + ks * 16;
            qh[ks][0] = *(const uint32_t*)(ph0 + c0);
            qh[ks][1] = *(const uint32_t*)(ph1 + c0);
            qh[ks][2] = *(const uint32_t*)(ph0 + c0 + 8);
            qh[ks][3] = *(const uint32_t*)(ph1 + c0 + 8);
            ql[ks][0] = *(const uint32_t*)(pl0 + c0);
            ql[ks][1] = *(const uint32_t*)(pl1 + c0);
            ql[ks][2] = *(const uint32_t*)(pl0 + c0 + 8);
            ql[ks][3] = *(const uint32_t*)(pl1 + c0 + 8);
        }
    }

    float o[8][4];
#pragma unroll
    for (int nd = 0; nd < 8; nd++)
#pragma unroll
        for (int c = 0; c < 4; c++) o[nd][c] = 0.0f;
    float m0 = -CUDART_INF_F, m1 = -CUDART_INF_F;
    float l0 = 0.0f, l1 = 0.0f;

    for (int kt = 0; kt <= qt; kt++) {
        const int s = kt & 1;
        if (kt + 1 <= qt) {
            load_stage(kt + 1, s ^ 1);
            CP_WAIT(1);
        } else {
            CP_WAIT(0);
        }
        __syncthreads();

        const uint32_t khiS = stgS + s * FT_STAGE;
        const uint32_t vhiS = khiS + FT_TILE;

        // ---- S = Q K^T (2-term) ----
        float sc[16][4];
#pragma unroll
        for (int nf = 0; nf < 16; nf++)
#pragma unroll
            for (int c = 0; c < 4; c++) sc[nf][c] = 0.0f;

#pragma unroll
        for (int ks = 0; ks < 4; ks++) {
            const int kb = ks * 32 + lc16;
#pragma unroll
            for (int kg = 0; kg < 2; kg++) {
                uint32_t tk[4][4];
#pragma unroll
                for (int j = 0; j < 4; j++) {
                    int kf = kg * 4 + j;
                    ldm_x4(tk[j], swz(khiS, kf * 16 + lrow, kb));
                }
#pragma unroll
                for (int j = 0; j < 4; j++) {
                    int kf = kg * 4 + j;
                    uint32_t b0[2] = {tk[j][0], tk[j][2]};
                    uint32_t b1[2] = {tk[j][1], tk[j][3]};
                    mma16816(sc[2 * kf],     qh[ks], b0);
                    mma16816(sc[2 * kf + 1], qh[ks], b1);
                }
#pragma unroll
                for (int j = 0; j < 4; j++) {
                    int kf = kg * 4 + j;
                    uint32_t b0[2] = {tk[j][0], tk[j][2]};
                    uint32_t b1[2] = {tk[j][1], tk[j][3]};
                    mma16816(sc[2 * kf],     ql[ks], b0);
                    mma16816(sc[2 * kf + 1], ql[ks], b1);
                }
            }
        }

        // ---- scale + causal mask + online softmax ----
        const float scale = 0.125f;
        const int rl0 = wid * 16 + g;
        const int rl1 = rl0 + 8;
        float rm0 = -CUDART_INF_F, rm1 = -CUDART_INF_F;
#pragma unroll
        for (int nf = 0; nf < 16; nf++) {
            float c0 = sc[nf][0] * scale, c1 = sc[nf][1] * scale;
            float c2 = sc[nf][2] * scale, c3 = sc[nf][3] * scale;
            if (kt == qt) {
                int col = nf * 8 + t2;
                if (col     > rl0) c0 = -1e30f;
                if (col + 1 > rl0) c1 = -1e30f;
                if (col     > rl1) c2 = -1e30f;
                if (col + 1 > rl1) c3 = -1e30f;
            }
            sc[nf][0] = c0; sc[nf][1] = c1; sc[nf][2] = c2; sc[nf][3] = c3;
            rm0 = fmaxf(rm0, fmaxf(c0, c1));
            rm1 = fmaxf(rm1, fmaxf(c2, c3));
        }
        rm0 = fmaxf(rm0, __shfl_xor_sync(0xffffffffu, rm0, 1));
        rm0 = fmaxf(rm0, __shfl_xor_sync(0xffffffffu, rm0, 2));
        rm1 = fmaxf(rm1, __shfl_xor_sync(0xffffffffu, rm1, 1));
        rm1 = fmaxf(rm1, __shfl_xor_sync(0xffffffffu, rm1, 2));

        const float mn0 = fmaxf(m0, rm0), mn1 = fmaxf(m1, rm1);
        const float a0 = __expf(m0 - mn0), a1 = __expf(m1 - mn1);
        float rs0 = 0.0f, rs1 = 0.0f;
#pragma unroll
        for (int nf = 0; nf < 16; nf++) {
            float p0 = __expf(sc[nf][0] - mn0);
            float p1 = __expf(sc[nf][1] - mn0);
            float p2 = __expf(sc[nf][2] - mn1);
            float p3 = __expf(sc[nf][3] - mn1);
            sc[nf][0] = p0; sc[nf][1] = p1; sc[nf][2] = p2; sc[nf][3] = p3;
            rs0 += p0 + p1;
            rs1 += p2 + p3;
        }
        rs0 += __shfl_xor_sync(0xffffffffu, rs0, 1);
        rs0 += __shfl_xor_sync(0xffffffffu, rs0, 2);
        rs1 += __shfl_xor_sync(0xffffffffu, rs1, 1);
        rs1 += __shfl_xor_sync(0xffffffffu, rs1, 2);
        l0 = l0 * a0 + rs0;
        l1 = l1 * a1 + rs1;
        m0 = mn0;
        m1 = mn1;
#pragma unroll
        for (int nd = 0; nd < 8; nd++) {
            o[nd][0] *= a0; o[nd][1] *= a0;
            o[nd][2] *= a1; o[nd][3] *= a1;
        }

        // ---- O += P V (2-term: (phi+plo) . vhi) ----
#pragma unroll
        for (int kk = 0; kk < 8; kk++) {
            float* p0 = sc[2 * kk];
            float* p1 = sc[2 * kk + 1];
            uint32_t phi[4], plo[4];
            phi[0] = pack_h2(p0[0], p0[1]);
            phi[1] = pack_h2(p0[2], p0[3]);
            phi[2] = pack_h2(p1[0], p1[1]);
            phi[3] = pack_h2(p1[2], p1[3]);
            plo[0] = pack_h2(h_res(p0[0]), h_res(p0[1]));
            plo[1] = pack_h2(h_res(p0[2]), h_res(p0[3]));
            plo[2] = pack_h2(h_res(p1[0]), h_res(p1[1]));
            plo[3] = pack_h2(h_res(p1[2]), h_res(p1[3]));

            uint32_t tv[4][4];
#pragma unroll
            for (int df = 0; df < 4; df++) {
                const int db = df * 32 + lc16;
                ldm_x4_t(tv[df], swz(vhiS, kk * 16 + lrow, db));
            }
#pragma unroll
            for (int df = 0; df < 4; df++) {
                uint32_t v0[2] = {tv[df][0], tv[df][1]};
                uint32_t v1[2] = {tv[df][2], tv[df][3]};
                mma16816(o[2 * df],     phi, v0);
                mma16816(o[2 * df + 1], phi, v1);
            }
#pragma unroll
            for (int df = 0; df < 4; df++) {
                uint32_t v0[2] = {tv[df][0], tv[df][1]};
                uint32_t v1[2] = {tv[df][2], tv[df][3]};
                mma16816(o[2 * df],     plo, v0);
                mma16816(o[2 * df + 1], plo, v1);
            }
        }
        __syncthreads();   // all warps done with stage s before overwrite
    }

    // ---- epilogue: normalize, split to fp16 hi/lo ----
    const float inv0 = 1.0f / l0;
    const float inv1 = 1.0f / l1;
    const size_t r0 = rowQ + wid * 16 + g;
    const size_t r1 = r0 + 8;
#pragma unroll
    for (int nd = 0; nd < 8; nd++) {
        int col = h * DD + nd * 8 + t2;
        float v0 = o[nd][0] * inv0, v1 = o[nd][1] * inv0;
        float v2 = o[nd][2] * inv1, v3 = o[nd][3] * inv1;
        size_t i0 = (r0 * CC + col) >> 1;
        size_t i1 = (r1 * CC + col) >> 1;
        ((uint32_t*)ohi)[i0] = pack_h2(v0, v1);
        ((uint32_t*)olo)[i0] = pack_h2(h_res(v0), h_res(v1));
        ((uint32_t*)ohi)[i1] = pack_h2(v2, v3);
        ((uint32_t*)olo)[i1] = pack_h2(h_res(v2), h_res(v3));
    }
}

// ---------------------------------------------------------------------------
// Launch
// ---------------------------------------------------------------------------
extern "C" void kernel_launch(void* const* d_in, const int* in_sizes, int n_in,
                              void* d_out, int out_size)
{
    (void)in_sizes; (void)n_in; (void)out_size;
    const float* x      = (const float*)d_in[0];
    const float* w_attn = (const float*)d_in[1];
    const float* b_attn = (const float*)d_in[2];
    const float* w_proj = (const float*)d_in[3];
    const float* b_proj = (const float*)d_in[4];
    float* out = (float*)d_out;

    __half *xhi, *xlo, *wahi, *wphi;
    __half *qkvhi, *qkvlo, *ahi, *alo;
    cudaGetSymbolAddress((void**)&xhi,   g_xhi);
    cudaGetSymbolAddress((void**)&xlo,   g_xlo);
    cudaGetSymbolAddress((void**)&wahi,  g_wahi);
    cudaGetSymbolAddress((void**)&wphi,  g_wphi);
    cudaGetSymbolAddress((void**)&qkvhi, g_qkvhi);
    cudaGetSymbolAddress((void**)&qkvlo, g_qkvlo);
    cudaGetSymbolAddress((void**)&ahi,   g_ahi);
    cudaGetSymbolAddress((void**)&alo,   g_alo);

    cudaFuncSetAttribute(gemm_mma_kernel,
                         cudaFuncAttributeMaxDynamicSharedMemorySize, GEMM_SMEM);
    cudaFuncSetAttribute(flash_mma_kernel,
                         cudaFuncAttributeMaxDynamicSharedMemorySize, FLASH_SMEM);

    // 1) split x -> fp16 hi/lo
    {
        int n4 = NTOK * CC / 4;
        split_fp32_kernel<<<(n4 + 255) / 256, 256>>>(x, xhi, xlo, n4);
    }
    // 2) transpose weights -> [N,K] fp16
    {
        dim3 blk(32, 8);
        split_transpose_kernel<<<dim3(QKVN / 32, CC / 32), blk>>>(w_attn, wahi, CC, QKVN);
        split_transpose_kernel<<<dim3(CC / 32, CC / 32), blk>>>(w_proj, wphi, CC, CC);
    }
    // 3) QKV GEMM -> split fp16 hi/lo qkv
    {
        dim3 grid(QKVN / 128, NTOK / 128);
        gemm_mma_kernel<<<grid, 256, GEMM_SMEM>>>(xhi, xlo, wahi,
                                                  b_attn, nullptr, qkvhi, qkvlo,
                                                  NTOK, QKVN, CC);
    }
    // 4) tensor-core flash attention -> split fp16 hi/lo y
    {
        dim3 grid(TT / 128, BB * HH);
        flash_mma_kernel<<<grid, 256, FLASH_SMEM>>>(qkvhi, qkvlo, ahi, alo);
    }
    // 5) proj GEMM -> fp32 out
    {
        dim3 grid(CC / 128, NTOK / 128);
        gemm_mma_kernel<<<grid, 256, GEMM_SMEM>>>(ahi, alo, wphi,
                                                  b_proj, out, nullptr, nullptr,
                                                  NTOK, CC, CC);
    }
}

// round 12
// speedup vs baseline: 1.0717x; 1.0045x over previous
#include <cuda_runtime.h>
#include <cuda_fp16.h>
#include <math_constants.h>
#include <cstdint>

// Problem constants
#define BB   2
#define TT   2048
#define CC   1024
#define HH   16
#define DD   64
#define NTOK (BB * TT)      // 4096
#define QKVN (3 * CC)       // 3072

// ---------------------------------------------------------------------------
// Scratch (no cudaMalloc allowed)
// ---------------------------------------------------------------------------
__device__ __half g_xhi[(size_t)NTOK * CC],  g_xlo[(size_t)NTOK * CC];
__device__ __half g_wahi[(size_t)QKVN * CC];               // [N,K] fp16(W)
__device__ __half g_wphi[(size_t)CC * CC];                 // [N,K] fp16(Wp)
__device__ __half g_qkvhi[(size_t)NTOK * QKVN], g_qkvlo[(size_t)NTOK * QKVN];
__device__ __half g_ahi[(size_t)NTOK * CC],  g_alo[(size_t)NTOK * CC];

// ---------------------------------------------------------------------------
// PTX helpers (plain-sm_103-legal: mma.sync / ldmatrix / cp.async)
// ---------------------------------------------------------------------------
__device__ __forceinline__ uint32_t smem_u32(const void* p) {
    uint32_t a;
    asm("{ .reg .u64 t; cvta.to.shared.u64 t, %1; cvt.u32.u64 %0, t; }"
        : "=r"(a) : "l"(p));
    return a;
}
__device__ __forceinline__ void ldm_x4(uint32_t* r, uint32_t addr) {
    asm volatile("ldmatrix.sync.aligned.m8n8.x4.shared.b16 {%0,%1,%2,%3}, [%4];"
                 : "=r"(r[0]), "=r"(r[1]), "=r"(r[2]), "=r"(r[3]) : "r"(addr));
}
__device__ __forceinline__ void ldm_x4_t(uint32_t* r, uint32_t addr) {
    asm volatile("ldmatrix.sync.aligned.m8n8.x4.trans.shared.b16 {%0,%1,%2,%3}, [%4];"
                 : "=r"(r[0]), "=r"(r[1]), "=r"(r[2]), "=r"(r[3]) : "r"(addr));
}
// fp16 MMA, fp32 accumulate
__device__ __forceinline__ void mma16816(float* d, const uint32_t* a, const uint32_t* b) {
    asm volatile(
        "mma.sync.aligned.m16n8k16.row.col.f32.f16.f16.f32 "
        "{%0,%1,%2,%3}, {%4,%5,%6,%7}, {%8,%9}, {%0,%1,%2,%3};"
        : "+f"(d[0]), "+f"(d[1]), "+f"(d[2]), "+f"(d[3])
        : "r"(a[0]), "r"(a[1]), "r"(a[2]), "r"(a[3]), "r"(b[0]), "r"(b[1]));
}
__device__ __forceinline__ void cp_async16(uint32_t sa, const void* g) {
    asm volatile("cp.async.ca.shared.global [%0], [%1], 16;" :: "r"(sa), "l"(g));
}
#define CP_COMMIT()  asm volatile("cp.async.commit_group;" ::: "memory")
#define CP_WAIT(n)   asm volatile("cp.async.wait_group %0;" :: "n"(n) : "memory")

// pack two fp32 into half2 (lo arg -> low 16 bits)
__device__ __forceinline__ uint32_t pack_h2(float lo, float hi) {
    __half2 h = __floats2half2_rn(lo, hi);
    return *(uint32_t*)&h;
}
__device__ __forceinline__ float h_res(float v) {
    return v - __half2float(__float2half_rn(v));
}
// 16B-granular XOR swizzle on 128-byte rows
__device__ __forceinline__ uint32_t swz(uint32_t base, int row, int bytecol) {
    return base + row * 128 + ((((bytecol >> 4) ^ (row & 7)) << 4));
}

// ---------------------------------------------------------------------------
// Fused preprocessing: split x -> fp16 hi/lo  |  transpose wa  |  transpose wp
// Grid sections: [0,4096) split-x, [4096,7168) wa, [7168,8192) wp.
// ---------------------------------------------------------------------------
#define PRE_SPLIT_BLKS 4096     // NTOK*CC/4 / 256
#define PRE_WA_BLKS    3072     // (QKVN/32)*(CC/32)
#define PRE_WP_BLKS    1024     // (CC/32)*(CC/32)
#define PRE_BLKS (PRE_SPLIT_BLKS + PRE_WA_BLKS + PRE_WP_BLKS)

__global__ __launch_bounds__(256) void preprocess_kernel(
    const float* __restrict__ x,  __half* __restrict__ xhi, __half* __restrict__ xlo,
    const float* __restrict__ wa, __half* __restrict__ wahi,
    const float* __restrict__ wp, __half* __restrict__ wphi)
{
    __shared__ float tile[32][33];
    const int blk = blockIdx.x;
    const int tid = threadIdx.x;

    if (blk < PRE_SPLIT_BLKS) {
        int i = blk * 256 + tid;
        float4 v = ((const float4*)x)[i];
        float vv[4] = {v.x, v.y, v.z, v.w};
        ushort4 sh, sl;
        unsigned short* ph = &sh.x;
        unsigned short* pl = &sl.x;
#pragma unroll
        for (int j = 0; j < 4; j++) {
            __half h = __float2half_rn(vv[j]);
            __half l = __float2half_rn(vv[j] - __half2float(h));
            ph[j] = __half_as_ushort(h);
            pl[j] = __half_as_ushort(l);
        }
        ((ushort4*)xhi)[i] = sh;
        ((ushort4*)xlo)[i] = sl;
        return;
    }

    // transpose section: fp32 [K,N] -> fp16 [N,K]
    const float* in;
    __half* out;
    int N, bid;
    if (blk < PRE_SPLIT_BLKS + PRE_WA_BLKS) {
        bid = blk - PRE_SPLIT_BLKS;
        in = wa; out = wahi; N = QKVN;
    } else {
        bid = blk - PRE_SPLIT_BLKS - PRE_WA_BLKS;
        in = wp; out = wphi; N = CC;
    }
    const int nbx = N / 32;
    const int bx = (bid % nbx) * 32;
    const int by = (bid / nbx) * 32;
    const int tx = tid & 31, ty = tid >> 5;   // 32 x 8
#pragma unroll
    for (int i = 0; i < 32; i += 8)
        tile[ty + i][tx] = in[(size_t)(by + ty + i) * N + bx + tx];
    __syncthreads();
#pragma unroll
    for (int i = 0; i < 32; i += 8) {
        float v = tile[tx][ty + i];
        out[(size_t)(bx + ty + i) * CC + by + tx] = __float2half_rn(v);
    }
}

// ---------------------------------------------------------------------------
// Split-fp16 2-term mma.sync GEMM: C[M,N] = (Ahi+Alo)[M,K] @ Bhi[N,K]^T + bias
// BK=64, XOR-swizzled 128B rows, 2-stage cp.async, 2 CTAs/SM.
// Warp tile 32x64 (wm 0..3, wn 0..1): A (2 sub-tiles) re-read only 2x.
// ---------------------------------------------------------------------------
#define GTILE  16384                 // 128 rows x 128 bytes (64 fp16)
#define GSTAGE (3 * GTILE)           // Ahi|Alo|Bhi = 48KB
#define GEMM_SMEM (2 * GSTAGE + 128)

__global__ __launch_bounds__(256, 2) void gemm_mma_kernel(
    const __half* __restrict__ Ahi, const __half* __restrict__ Alo,
    const __half* __restrict__ Bhi,
    const float* __restrict__ bias, float* __restrict__ Cf,
    __half* __restrict__ Chi, __half* __restrict__ Clo,
    int M, int N, int K)
{
    extern __shared__ char dsm[];
    const uint32_t dynb = smem_u32(dsm);
    const uint32_t sb_u = (dynb + 127) & ~127u;

    const int tid  = threadIdx.x;
    const int wid  = tid >> 5;
    const int lane = tid & 31;
    const int wm   = wid & 3;            // 0..3 : 32-row strip
    const int wn   = wid >> 2;           // 0..1 : 64-col strip
    const int m0 = blockIdx.y * 128;
    const int n0 = blockIdx.x * 128;

    const int lrow = lane & 15;
    const int lc16 = (lane >> 4) << 4;   // +16B for lanes >= 16

    float acc[2][8][4];
#pragma unroll
    for (int a = 0; a < 2; a++)
#pragma unroll
        for (int b = 0; b < 8; b++)
#pragma unroll
            for (int c = 0; c < 4; c++) acc[a][b][c] = 0.0f;

    const int nCh = K >> 6;   // BK = 64

    auto load_stage = [&](int c, int s) {
        const int kc = c << 6;
#pragma unroll
        for (int it = 0; it < 12; it++) {
            int i    = it * 256 + tid;      // 0..3071
            int tile = i >> 10;             // 0..2 : Ahi, Alo, Bhi
            int w    = i & 1023;
            int row  = w >> 3;              // 0..127
            int slot = w & 7;               // 16B slots (8 per row)
            const __half* gp;
            if      (tile == 0) gp = Ahi + (size_t)(m0 + row) * K + kc + slot * 8;
            else if (tile == 1) gp = Alo + (size_t)(m0 + row) * K + kc + slot * 8;
            else                gp = Bhi + (size_t)(n0 + row) * K + kc + slot * 8;
            cp_async16(swz(sb_u + s * GSTAGE + tile * GTILE, row, slot * 16), gp);
        }
        CP_COMMIT();
    };

    auto compute = [&](int s) {
        const uint32_t aHi = sb_u + s * GSTAGE;
        const uint32_t aLo = aHi + GTILE;
        const uint32_t bHi = aHi + 2 * GTILE;
#pragma unroll
        for (int ks = 0; ks < 4; ks++) {
            const int kb = ks * 32 + lc16;
            // B fragments: 64 cols = 4 ldmatrix.x4 -> 8 n-frags
            uint32_t bhi[8][2];
#pragma unroll
            for (int bg = 0; bg < 4; bg++) {
                int row = wn * 64 + bg * 16 + lrow;
                uint32_t t[4];
                ldm_x4(t, swz(bHi, row, kb));
                bhi[bg * 2][0] = t[0]; bhi[bg * 2 + 1][0] = t[1];
                bhi[bg * 2][1] = t[2]; bhi[bg * 2 + 1][1] = t[3];
            }
            // hi pass
            {
                uint32_t ahi[2][4];
#pragma unroll
                for (int mi = 0; mi < 2; mi++)
                    ldm_x4(ahi[mi], swz(aHi, wm * 32 + mi * 16 + lrow, kb));
#pragma unroll
                for (int mi = 0; mi < 2; mi++)
#pragma unroll
                    for (int nf = 0; nf < 8; nf++)
                        mma16816(acc[mi][nf], ahi[mi], bhi[nf]);
            }
            // lo pass
            {
                uint32_t alo[2][4];
#pragma unroll
                for (int mi = 0; mi < 2; mi++)
                    ldm_x4(alo[mi], swz(aLo, wm * 32 + mi * 16 + lrow, kb));
#pragma unroll
                for (int mi = 0; mi < 2; mi++)
#pragma unroll
                    for (int nf = 0; nf < 8; nf++)
                        mma16816(acc[mi][nf], alo[mi], bhi[nf]);
            }
        }
    };

    // 2-stage pipeline
    load_stage(0, 0);
    for (int c = 0; c < nCh; c++) {
        const int s = c & 1;
        __syncthreads();
        if (c + 1 < nCh) {
            load_stage(c + 1, s ^ 1);
            CP_WAIT(1);
        } else {
            CP_WAIT(0);
        }
        __syncthreads();
        compute(s);
    }

    const int g = lane >> 2;
    const int t2 = (lane & 3) * 2;
#pragma unroll
    for (int mf = 0; mf < 2; mf++) {
#pragma unroll
        for (int nf = 0; nf < 8; nf++) {
            int col = n0 + wn * 64 + nf * 8 + t2;
            float2 bv = *(const float2*)(bias + col);
            int r0 = m0 + wm * 32 + mf * 16 + g;
            float v0 = acc[mf][nf][0] + bv.x, v1 = acc[mf][nf][1] + bv.y;
            float v2 = acc[mf][nf][2] + bv.x, v3 = acc[mf][nf][3] + bv.y;
            if (Chi) {
                size_t i0 = ((size_t)r0 * N + col) >> 1;
                size_t i1 = ((size_t)(r0 + 8) * N + col) >> 1;
                ((uint32_t*)Chi)[i0] = pack_h2(v0, v1);
                ((uint32_t*)Clo)[i0] = pack_h2(h_res(v0), h_res(v1));
                ((uint32_t*)Chi)[i1] = pack_h2(v2, v3);
                ((uint32_t*)Clo)[i1] = pack_h2(h_res(v2), h_res(v3));
            } else {
                float2 o0 = {v0, v1}, o1 = {v2, v3};
                *(float2*)(Cf + (size_t)r0 * N + col)       = o0;
                *(float2*)(Cf + (size_t)(r0 + 8) * N + col) = o1;
            }
        }
    }
}

// ---------------------------------------------------------------------------
// Tensor-core flash attention (causal), fp16 2-term (unchanged R10 version):
//   S = (qhi+qlo) . khi ;  O = (phi+plo) . vhi
// ---------------------------------------------------------------------------
#define FT_TILE 16384                       // 128 x 64 fp16
#define FT_STAGE (2 * FT_TILE)              // Khi|Vhi = 32KB
#define FLASH_SMEM (2 * FT_STAGE + 128)

__global__ __launch_bounds__(256, 1) void flash_mma_kernel(
    const __half* __restrict__ qkvhi,
    const __half* __restrict__ qkvlo,
    __half* __restrict__ ohi,
    __half* __restrict__ olo)
{
    extern __shared__ char dsm[];
    const uint32_t dynb = smem_u32(dsm);
    const uint32_t stgS = (dynb + 127) & ~127u;

    const int tid  = threadIdx.x;
    const int wid  = tid >> 5;
    const int lane = tid & 31;
    const int lrow = lane & 15;
    const int lc16 = (lane >> 4) << 4;
    const int g    = lane >> 2;
    const int t2   = (lane & 3) * 2;

    const int b  = blockIdx.y >> 4;
    const int h  = blockIdx.y & 15;
    const int qt = (int)gridDim.x - 1 - (int)blockIdx.x;

    const size_t rowQ = (size_t)(b * TT + qt * 128);
    const int qcol = h * DD;
    const int kcol = CC + h * DD;
    const int vcol = 2 * CC + h * DD;

    auto load_stage = [&](int kt, int s) {
        const size_t rowK = (size_t)(b * TT + kt * 128);
        const uint32_t st = stgS + s * FT_STAGE;
#pragma unroll
        for (int it = 0; it < 8; it++) {
            int i = it * 256 + tid;      // 0..2047
            int t = i >> 10;             // 0 = Khi, 1 = Vhi
            int w = i & 1023;
            int r = w >> 3, c = w & 7;
            int colb = t ? vcol : kcol;
            cp_async16(swz(st + t * FT_TILE, r, c * 16),
                       qkvhi + (rowK + r) * QKVN + colb + c * 8);
        }
        CP_COMMIT();
    };

    load_stage(0, 0);

    // ---- Q hi/lo fragments direct from gmem ----
    uint32_t qh[4][4], ql[4][4];
    {
        const size_t r0 = rowQ + wid * 16 + g;
        const size_t r1 = r0 + 8;
        const __half* ph0 = qkvhi + r0 * QKVN + qcol;
        const __half* ph1 = qkvhi + r1 * QKVN + qcol;
        const __half* pl0 = qkvlo + r0 * QKVN + qcol;
        const __half* pl1 = qkvlo + r1 * QKVN + qcol;
#pragma unroll
        for (int ks = 0; ks < 4; ks++) {
            int c0 = t2 + ks * 16;
            qh[ks][0] = *(const uint32_t*)(ph0 + c0);
            qh[ks][1] = *(const uint32_t*)(ph1 + c0);
            qh[ks][2] = *(const uint32_t*)(ph0 + c0 + 8);
            qh[ks][3] = *(const uint32_t*)(ph1 + c0 + 8);
            ql[ks][0] = *(const uint32_t*)(pl0 + c0);
            ql[ks][1] = *(const uint32_t*)(pl1 + c0);
            ql[ks][2] = *(const uint32_t*)(pl0 + c0 + 8);
            ql[ks][3] = *(const uint32_t*)(pl1 + c0 + 8);
        }
    }

    float o[8][4];
#pragma unroll
    for (int nd = 0; nd < 8; nd++)
#pragma unroll
        for (int c = 0; c < 4; c++) o[nd][c] = 0.0f;
    float m0 = -CUDART_INF_F, m1 = -CUDART_INF_F;
    float l0 = 0.0f, l1 = 0.0f;

    for (int kt = 0; kt <= qt; kt++) {
        const int s = kt & 1;
        if (kt + 1 <= qt) {
            load_stage(kt + 1, s ^ 1);
            CP_WAIT(1);
        } else {
            CP_WAIT(0);
        }
        __syncthreads();

        const uint32_t khiS = stgS + s * FT_STAGE;
        const uint32_t vhiS = khiS + FT_TILE;

        // ---- S = Q K^T (2-term) ----
        float sc[16][4];
#pragma unroll
        for (int nf = 0; nf < 16; nf++)
#pragma unroll
            for (int c = 0; c < 4; c++) sc[nf][c] = 0.0f;

#pragma unroll
        for (int ks = 0; ks < 4; ks++) {
            const int kb = ks * 32 + lc16;
#pragma unroll
            for (int kg = 0; kg < 2; kg++) {
                uint32_t tk[4][4];
#pragma unroll
                for (int j = 0; j < 4; j++) {
                    int kf = kg * 4 + j;
                    ldm_x4(tk[j], swz(khiS, kf * 16 + lrow, kb));
                }
#pragma unroll
                for (int j = 0; j < 4; j++) {
                    int kf = kg * 4 + j;
                    uint32_t b0[2] = {tk[j][0], tk[j][2]};
                    uint32_t b1[2] = {tk[j][1], tk[j][3]};
                    mma16816(sc[2 * kf],     qh[ks], b0);
                    mma16816(sc[2 * kf + 1], qh[ks], b1);
                }
#pragma unroll
                for (int j = 0; j < 4; j++) {
                    int kf = kg * 4 + j;
                    uint32_t b0[2] = {tk[j][0], tk[j][2]};
                    uint32_t b1[2] = {tk[j][1], tk[j][3]};
                    mma16816(sc[2 * kf],     ql[ks], b0);
                    mma16816(sc[2 * kf + 1], ql[ks], b1);
                }
            }
        }

        // ---- scale + causal mask + online softmax ----
        const float scale = 0.125f;
        const int rl0 = wid * 16 + g;
        const int rl1 = rl0 + 8;
        float rm0 = -CUDART_INF_F, rm1 = -CUDART_INF_F;
#pragma unroll
        for (int nf = 0; nf < 16; nf++) {
            float c0 = sc[nf][0] * scale, c1 = sc[nf][1] * scale;
            float c2 = sc[nf][2] * scale, c3 = sc[nf][3] * scale;
            if (kt == qt) {
                int col = nf * 8 + t2;
                if (col     > rl0) c0 = -1e30f;
                if (col + 1 > rl0) c1 = -1e30f;
                if (col     > rl1) c2 = -1e30f;
                if (col + 1 > rl1) c3 = -1e30f;
            }
            sc[nf][0] = c0; sc[nf][1] = c1; sc[nf][2] = c2; sc[nf][3] = c3;
            rm0 = fmaxf(rm0, fmaxf(c0, c1));
            rm1 = fmaxf(rm1, fmaxf(c2, c3));
        }
        rm0 = fmaxf(rm0, __shfl_xor_sync(0xffffffffu, rm0, 1));
        rm0 = fmaxf(rm0, __shfl_xor_sync(0xffffffffu, rm0, 2));
        rm1 = fmaxf(rm1, __shfl_xor_sync(0xffffffffu, rm1, 1));
        rm1 = fmaxf(rm1, __shfl_xor_sync(0xffffffffu, rm1, 2));

        const float mn0 = fmaxf(m0, rm0), mn1 = fmaxf(m1, rm1);
        const float a0 = __expf(m0 - mn0), a1 = __expf(m1 - mn1);
        float rs0 = 0.0f, rs1 = 0.0f;
#pragma unroll
        for (int nf = 0; nf < 16; nf++) {
            float p0 = __expf(sc[nf][0] - mn0);
            float p1 = __expf(sc[nf][1] - mn0);
            float p2 = __expf(sc[nf][2] - mn1);
            float p3 = __expf(sc[nf][3] - mn1);
            sc[nf][0] = p0; sc[nf][1] = p1; sc[nf][2] = p2; sc[nf][3] = p3;
            rs0 += p0 + p1;
            rs1 += p2 + p3;
        }
        rs0 += __shfl_xor_sync(0xffffffffu, rs0, 1);
        rs0 += __shfl_xor_sync(0xffffffffu, rs0, 2);
        rs1 += __shfl_xor_sync(0xffffffffu, rs1, 1);
        rs1 += __shfl_xor_sync(0xffffffffu, rs1, 2);
        l0 = l0 * a0 + rs0;
        l1 = l1 * a1 + rs1;
        m0 = mn0;
        m1 = mn1;
#pragma unroll
        for (int nd = 0; nd < 8; nd++) {
            o[nd][0] *= a0; o[nd][1] *= a0;
            o[nd][2] *= a1; o[nd][3] *= a1;
        }

        // ---- O += P V (2-term: (phi+plo) . vhi) ----
#pragma unroll
        for (int kk = 0; kk < 8; kk++) {
            float* p0 = sc[2 * kk];
            float* p1 = sc[2 * kk + 1];
            uint32_t phi[4], plo[4];
            phi[0] = pack_h2(p0[0], p0[1]);
            phi[1] = pack_h2(p0[2], p0[3]);
            phi[2] = pack_h2(p1[0], p1[1]);
            phi[3] = pack_h2(p1[2], p1[3]);
            plo[0] = pack_h2(h_res(p0[0]), h_res(p0[1]));
            plo[1] = pack_h2(h_res(p0[2]), h_res(p0[3]));
            plo[2] = pack_h2(h_res(p1[0]), h_res(p1[1]));
            plo[3] = pack_h2(h_res(p1[2]), h_res(p1[3]));

            uint32_t tv[4][4];
#pragma unroll
            for (int df = 0; df < 4; df++) {
                const int db = df * 32 + lc16;
                ldm_x4_t(tv[df], swz(vhiS, kk * 16 + lrow, db));
            }
#pragma unroll
            for (int df = 0; df < 4; df++) {
                uint32_t v0[2] = {tv[df][0], tv[df][1]};
                uint32_t v1[2] = {tv[df][2], tv[df][3]};
                mma16816(o[2 * df],     phi, v0);
                mma16816(o[2 * df + 1], phi, v1);
            }
#pragma unroll
            for (int df = 0; df < 4; df++) {
                uint32_t v0[2] = {tv[df][0], tv[df][1]};
                uint32_t v1[2] = {tv[df][2], tv[df][3]};
                mma16816(o[2 * df],     plo, v0);
                mma16816(o[2 * df + 1], plo, v1);
            }
        }
        __syncthreads();   // all warps done with stage s before overwrite
    }

    // ---- epilogue: normalize, split to fp16 hi/lo ----
    const float inv0 = 1.0f / l0;
    const float inv1 = 1.0f / l1;
    const size_t r0 = rowQ + wid * 16 + g;
    const size_t r1 = r0 + 8;
#pragma unroll
    for (int nd = 0; nd < 8; nd++) {
        int col = h * DD + nd * 8 + t2;
        float v0 = o[nd][0] * inv0, v1 = o[nd][1] * inv0;
        float v2 = o[nd][2] * inv1, v3 = o[nd][3] * inv1;
        size_t i0 = (r0 * CC + col) >> 1;
        size_t i1 = (r1 * CC + col) >> 1;
        ((uint32_t*)ohi)[i0] = pack_h2(v0, v1);
        ((uint32_t*)olo)[i0] = pack_h2(h_res(v0), h_res(v1));
        ((uint32_t*)ohi)[i1] = pack_h2(v2, v3);
        ((uint32_t*)olo)[i1] = pack_h2(h_res(v2), h_res(v3));
    }
}

// ---------------------------------------------------------------------------
// Launch
// ---------------------------------------------------------------------------
extern "C" void kernel_launch(void* const* d_in, const int* in_sizes, int n_in,
                              void* d_out, int out_size)
{
    (void)in_sizes; (void)n_in; (void)out_size;
    const float* x      = (const float*)d_in[0];
    const float* w_attn = (const float*)d_in[1];
    const float* b_attn = (const float*)d_in[2];
    const float* w_proj = (const float*)d_in[3];
    const float* b_proj = (const float*)d_in[4];
    float* out = (float*)d_out;

    __half *xhi, *xlo, *wahi, *wphi;
    __half *qkvhi, *qkvlo, *ahi, *alo;
    cudaGetSymbolAddress((void**)&xhi,   g_xhi);
    cudaGetSymbolAddress((void**)&xlo,   g_xlo);
    cudaGetSymbolAddress((void**)&wahi,  g_wahi);
    cudaGetSymbolAddress((void**)&wphi,  g_wphi);
    cudaGetSymbolAddress((void**)&qkvhi, g_qkvhi);
    cudaGetSymbolAddress((void**)&qkvlo, g_qkvlo);
    cudaGetSymbolAddress((void**)&ahi,   g_ahi);
    cudaGetSymbolAddress((void**)&alo,   g_alo);

    cudaFuncSetAttribute(gemm_mma_kernel,
                         cudaFuncAttributeMaxDynamicSharedMemorySize, GEMM_SMEM);
    cudaFuncSetAttribute(flash_mma_kernel,
                         cudaFuncAttributeMaxDynamicSharedMemorySize, FLASH_SMEM);

    // 1) fused preprocessing: split x + transpose both weights
    preprocess_kernel<<<PRE_BLKS, 256>>>(x, xhi, xlo, w_attn, wahi, w_proj, wphi);

    // 2) QKV GEMM -> split fp16 hi/lo qkv
    {
        dim3 grid(QKVN / 128, NTOK / 128);
        gemm_mma_kernel<<<grid, 256, GEMM_SMEM>>>(xhi, xlo, wahi,
                                                  b_attn, nullptr, qkvhi, qkvlo,
                                                  NTOK, QKVN, CC);
    }
    // 3) tensor-core flash attention -> split fp16 hi/lo y
    {
        dim3 grid(TT / 128, BB * HH);
        flash_mma_kernel<<<grid, 256, FLASH_SMEM>>>(qkvhi, qkvlo, ahi, alo);
    }
    // 4) proj GEMM -> fp32 out
    {
        dim3 grid(CC / 128, NTOK / 128);
        gemm_mma_kernel<<<grid, 256, GEMM_SMEM>>>(ahi, alo, wphi,
                                                  b_proj, out, nullptr, nullptr,
                                                  NTOK, CC, CC);
    }
}

// round 17
// speedup vs baseline: 1.1813x; 1.1022x over previous
#include <cuda_runtime.h>
#include <cuda_fp16.h>
#include <math_constants.h>
#include <cstdint>

// Problem constants
#define BB   2
#define TT   2048
#define CC   1024
#define HH   16
#define DD   64
#define NTOK (BB * TT)      // 4096
#define QKVN (3 * CC)       // 3072

// ---------------------------------------------------------------------------
// Scratch (no cudaMalloc allowed)
// ---------------------------------------------------------------------------
__device__ __half g_xhi[(size_t)NTOK * CC],  g_xlo[(size_t)NTOK * CC];
__device__ __half g_wahi[(size_t)QKVN * CC];               // [N,K] fp16(W)
__device__ __half g_wphi[(size_t)CC * CC];                 // [N,K] fp16(Wp)
__device__ __half g_qkvhi[(size_t)NTOK * QKVN], g_qkvlo[(size_t)NTOK * QKVN];
__device__ __half g_ahi[(size_t)NTOK * CC],  g_alo[(size_t)NTOK * CC];

// ---------------------------------------------------------------------------
// PTX helpers (plain-sm_103-legal: mma.sync / ldmatrix / cp.async)
// ---------------------------------------------------------------------------
__device__ __forceinline__ uint32_t smem_u32(const void* p) {
    uint32_t a;
    asm("{ .reg .u64 t; cvta.to.shared.u64 t, %1; cvt.u32.u64 %0, t; }"
        : "=r"(a) : "l"(p));
    return a;
}
__device__ __forceinline__ void ldm_x4(uint32_t* r, uint32_t addr) {
    asm volatile("ldmatrix.sync.aligned.m8n8.x4.shared.b16 {%0,%1,%2,%3}, [%4];"
                 : "=r"(r[0]), "=r"(r[1]), "=r"(r[2]), "=r"(r[3]) : "r"(addr));
}
__device__ __forceinline__ void ldm_x4_t(uint32_t* r, uint32_t addr) {
    asm volatile("ldmatrix.sync.aligned.m8n8.x4.trans.shared.b16 {%0,%1,%2,%3}, [%4];"
                 : "=r"(r[0]), "=r"(r[1]), "=r"(r[2]), "=r"(r[3]) : "r"(addr));
}
// fp16 MMA, fp32 accumulate
__device__ __forceinline__ void mma16816(float* d, const uint32_t* a, const uint32_t* b) {
    asm volatile(
        "mma.sync.aligned.m16n8k16.row.col.f32.f16.f16.f32 "
        "{%0,%1,%2,%3}, {%4,%5,%6,%7}, {%8,%9}, {%0,%1,%2,%3};"
        : "+f"(d[0]), "+f"(d[1]), "+f"(d[2]), "+f"(d[3])
        : "r"(a[0]), "r"(a[1]), "r"(a[2]), "r"(a[3]), "r"(b[0]), "r"(b[1]));
}
__device__ __forceinline__ void cp_async16(uint32_t sa, const void* g) {
    asm volatile("cp.async.ca.shared.global [%0], [%1], 16;" :: "r"(sa), "l"(g));
}
#define CP_COMMIT()  asm volatile("cp.async.commit_group;" ::: "memory")
#define CP_WAIT(n)   asm volatile("cp.async.wait_group %0;" :: "n"(n) : "memory")

// pack two fp32 into half2 (lo arg -> low 16 bits)
__device__ __forceinline__ uint32_t pack_h2(float lo, float hi) {
    __half2 h = __floats2half2_rn(lo, hi);
    return *(uint32_t*)&h;
}
__device__ __forceinline__ float h_res(float v) {
    return v - __half2float(__float2half_rn(v));
}
// 16B-granular XOR swizzle on 128-byte rows
__device__ __forceinline__ uint32_t swz(uint32_t base, int row, int bytecol) {
    return base + row * 128 + ((((bytecol >> 4) ^ (row & 7)) << 4));
}

// ---------------------------------------------------------------------------
// Fused preprocessing: split x -> fp16 hi/lo  |  transpose wa  |  transpose wp
// ---------------------------------------------------------------------------
#define PRE_SPLIT_BLKS 4096     // NTOK*CC/4 / 256
#define PRE_WA_BLKS    3072     // (QKVN/32)*(CC/32)
#define PRE_WP_BLKS    1024     // (CC/32)*(CC/32)
#define PRE_BLKS (PRE_SPLIT_BLKS + PRE_WA_BLKS + PRE_WP_BLKS)

__global__ __launch_bounds__(256) void preprocess_kernel(
    const float* __restrict__ x,  __half* __restrict__ xhi, __half* __restrict__ xlo,
    const float* __restrict__ wa, __half* __restrict__ wahi,
    const float* __restrict__ wp, __half* __restrict__ wphi)
{
    __shared__ float tile[32][33];
    const int blk = blockIdx.x;
    const int tid = threadIdx.x;

    if (blk < PRE_SPLIT_BLKS) {
        int i = blk * 256 + tid;
        float4 v = ((const float4*)x)[i];
        float vv[4] = {v.x, v.y, v.z, v.w};
        ushort4 sh, sl;
        unsigned short* ph = &sh.x;
        unsigned short* pl = &sl.x;
#pragma unroll
        for (int j = 0; j < 4; j++) {
            __half h = __float2half_rn(vv[j]);
            __half l = __float2half_rn(vv[j] - __half2float(h));
            ph[j] = __half_as_ushort(h);
            pl[j] = __half_as_ushort(l);
        }
        ((ushort4*)xhi)[i] = sh;
        ((ushort4*)xlo)[i] = sl;
        return;
    }

    // transpose section: fp32 [K,N] -> fp16 [N,K]
    const float* in;
    __half* out;
    int N, bid;
    if (blk < PRE_SPLIT_BLKS + PRE_WA_BLKS) {
        bid = blk - PRE_SPLIT_BLKS;
        in = wa; out = wahi; N = QKVN;
    } else {
        bid = blk - PRE_SPLIT_BLKS - PRE_WA_BLKS;
        in = wp; out = wphi; N = CC;
    }
    const int nbx = N / 32;
    const int bx = (bid % nbx) * 32;
    const int by = (bid / nbx) * 32;
    const int tx = tid & 31, ty = tid >> 5;   // 32 x 8
#pragma unroll
    for (int i = 0; i < 32; i += 8)
        tile[ty + i][tx] = in[(size_t)(by + ty + i) * N + bx + tx];
    __syncthreads();
#pragma unroll
    for (int i = 0; i < 32; i += 8) {
        float v = tile[tx][ty + i];
        out[(size_t)(bx + ty + i) * CC + by + tx] = __float2half_rn(v);
    }
}

// ---------------------------------------------------------------------------
// Split-fp16 mma.sync GEMM: C[M,N] = (Ahi[+Alo])[M,K] @ Bhi[N,K]^T + bias
// Blocks with n0 >= n2term use 1-term A (hi only): half the MMA work.
// BK=64, XOR-swizzled 128B rows, 2-stage cp.async, 2 CTAs/SM.
// ---------------------------------------------------------------------------
#define GTILE  16384                 // 128 rows x 128 bytes (64 fp16)
#define GSTAGE (3 * GTILE)           // Ahi|Alo|Bhi = 48KB
#define GEMM_SMEM (2 * GSTAGE + 128)

__global__ __launch_bounds__(256, 2) void gemm_mma_kernel(
    const __half* __restrict__ Ahi, const __half* __restrict__ Alo,
    const __half* __restrict__ Bhi,
    const float* __restrict__ bias, float* __restrict__ Cf,
    __half* __restrict__ Chi, __half* __restrict__ Clo,
    int M, int N, int K, int n2term)
{
    extern __shared__ char dsm[];
    const uint32_t dynb = smem_u32(dsm);
    const uint32_t sb_u = (dynb + 127) & ~127u;

    const int tid  = threadIdx.x;
    const int wid  = tid >> 5;
    const int lane = tid & 31;
    const int wm   = wid & 3;            // 0..3 : 32-row strip
    const int wn   = wid >> 2;           // 0..1 : 64-col strip
    const int m0 = blockIdx.y * 128;
    const int n0 = blockIdx.x * 128;
    const bool do_lo = (n0 < n2term);    // uniform per block

    const int lrow = lane & 15;
    const int lc16 = (lane >> 4) << 4;   // +16B for lanes >= 16

    float acc[2][8][4];
#pragma unroll
    for (int a = 0; a < 2; a++)
#pragma unroll
        for (int b = 0; b < 8; b++)
#pragma unroll
            for (int c = 0; c < 4; c++) acc[a][b][c] = 0.0f;

    const int nCh = K >> 6;   // BK = 64

    auto load_stage = [&](int c, int s) {
        const int kc = c << 6;
#pragma unroll
        for (int it = 0; it < 12; it++) {
            int i    = it * 256 + tid;      // 0..3071
            int tile = i >> 10;             // 0..2 : Ahi, Alo, Bhi
            int w    = i & 1023;
            int row  = w >> 3;              // 0..127
            int slot = w & 7;               // 16B slots (8 per row)
            if (tile == 1 && !do_lo) continue;   // 1-term blocks skip Alo
            const __half* gp;
            if      (tile == 0) gp = Ahi + (size_t)(m0 + row) * K + kc + slot * 8;
            else if (tile == 1) gp = Alo + (size_t)(m0 + row) * K + kc + slot * 8;
            else                gp = Bhi + (size_t)(n0 + row) * K + kc + slot * 8;
            cp_async16(swz(sb_u + s * GSTAGE + tile * GTILE, row, slot * 16), gp);
        }
        CP_COMMIT();
    };

    auto compute = [&](int s) {
        const uint32_t aHi = sb_u + s * GSTAGE;
        const uint32_t aLo = aHi + GTILE;
        const uint32_t bHi = aHi + 2 * GTILE;
#pragma unroll
        for (int ks = 0; ks < 4; ks++) {
            const int kb = ks * 32 + lc16;
            // B fragments: 64 cols = 4 ldmatrix.x4 -> 8 n-frags
            uint32_t bhi[8][2];
#pragma unroll
            for (int bg = 0; bg < 4; bg++) {
                int row = wn * 64 + bg * 16 + lrow;
                uint32_t t[4];
                ldm_x4(t, swz(bHi, row, kb));
                bhi[bg * 2][0] = t[0]; bhi[bg * 2 + 1][0] = t[1];
                bhi[bg * 2][1] = t[2]; bhi[bg * 2 + 1][1] = t[3];
            }
            // hi pass
            {
                uint32_t ahi[2][4];
#pragma unroll
                for (int mi = 0; mi < 2; mi++)
                    ldm_x4(ahi[mi], swz(aHi, wm * 32 + mi * 16 + lrow, kb));
#pragma unroll
                for (int mi = 0; mi < 2; mi++)
#pragma unroll
                    for (int nf = 0; nf < 8; nf++)
                        mma16816(acc[mi][nf], ahi[mi], bhi[nf]);
            }
            // lo pass (only for 2-term blocks)
            if (do_lo) {
                uint32_t alo[2][4];
#pragma unroll
                for (int mi = 0; mi < 2; mi++)
                    ldm_x4(alo[mi], swz(aLo, wm * 32 + mi * 16 + lrow, kb));
#pragma unroll
                for (int mi = 0; mi < 2; mi++)
#pragma unroll
                    for (int nf = 0; nf < 8; nf++)
                        mma16816(acc[mi][nf], alo[mi], bhi[nf]);
            }
        }
    };

    // 2-stage pipeline
    load_stage(0, 0);
    for (int c = 0; c < nCh; c++) {
        const int s = c & 1;
        __syncthreads();
        if (c + 1 < nCh) {
            load_stage(c + 1, s ^ 1);
            CP_WAIT(1);
        } else {
            CP_WAIT(0);
        }
        __syncthreads();
        compute(s);
    }

    const int g = lane >> 2;
    const int t2 = (lane & 3) * 2;
#pragma unroll
    for (int mf = 0; mf < 2; mf++) {
#pragma unroll
        for (int nf = 0; nf < 8; nf++) {
            int col = n0 + wn * 64 + nf * 8 + t2;
            float2 bv = *(const float2*)(bias + col);
            int r0 = m0 + wm * 32 + mf * 16 + g;
            float v0 = acc[mf][nf][0] + bv.x, v1 = acc[mf][nf][1] + bv.y;
            float v2 = acc[mf][nf][2] + bv.x, v3 = acc[mf][nf][3] + bv.y;
            if (Chi) {
                size_t i0 = ((size_t)r0 * N + col) >> 1;
                size_t i1 = ((size_t)(r0 + 8) * N + col) >> 1;
                ((uint32_t*)Chi)[i0] = pack_h2(v0, v1);
                ((uint32_t*)Clo)[i0] = pack_h2(h_res(v0), h_res(v1));
                ((uint32_t*)Chi)[i1] = pack_h2(v2, v3);
                ((uint32_t*)Clo)[i1] = pack_h2(h_res(v2), h_res(v3));
            } else {
                float2 o0 = {v0, v1}, o1 = {v2, v3};
                *(float2*)(Cf + (size_t)r0 * N + col)       = o0;
                *(float2*)(Cf + (size_t)(r0 + 8) * N + col) = o1;
            }
        }
    }
}

// ---------------------------------------------------------------------------
// Tensor-core flash attention (causal), fp16 2-term:
//   S = (qhi+qlo) . khi ;  O = (phi+plo) . vhi
// ---------------------------------------------------------------------------
#define FT_TILE 16384                       // 128 x 64 fp16
#define FT_STAGE (2 * FT_TILE)              // Khi|Vhi = 32KB
#define FLASH_SMEM (2 * FT_STAGE + 128)

__global__ __launch_bounds__(256, 1) void flash_mma_kernel(
    const __half* __restrict__ qkvhi,
    const __half* __restrict__ qkvlo,
    __half* __restrict__ ohi,
    __half* __restrict__ olo)
{
    extern __shared__ char dsm[];
    const uint32_t dynb = smem_u32(dsm);
    const uint32_t stgS = (dynb + 127) & ~127u;

    const int tid  = threadIdx.x;
    const int wid  = tid >> 5;
    const int lane = tid & 31;
    const int lrow = lane & 15;
    const int lc16 = (lane >> 4) << 4;
    const int g    = lane >> 2;
    const int t2   = (lane & 3) * 2;

    const int b  = blockIdx.y >> 4;
    const int h  = blockIdx.y & 15;
    const int qt = (int)gridDim.x - 1 - (int)blockIdx.x;

    const size_t rowQ = (size_t)(b * TT + qt * 128);
    const int qcol = h * DD;
    const int kcol = CC + h * DD;
    const int vcol = 2 * CC + h * DD;

    auto load_stage = [&](int kt, int s) {
        const size_t rowK = (size_t)(b * TT + kt * 128);
        const uint32_t st = stgS + s * FT_STAGE;
#pragma unroll
        for (int it = 0; it < 8; it++) {
            int i = it * 256 + tid;      // 0..2047
            int t = i >> 10;             // 0 = Khi, 1 = Vhi
            int w = i & 1023;
            int r = w >> 3, c = w & 7;
            int colb = t ? vcol : kcol;
            cp_async16(swz(st + t * FT_TILE, r, c * 16),
                       qkvhi + (rowK + r) * QKVN + colb + c * 8);
        }
        CP_COMMIT();
    };

    load_stage(0, 0);

    // ---- Q hi/lo fragments direct from gmem ----
    uint32_t qh[4][4], ql[4][4];
    {
        const size_t r0 = rowQ + wid * 16 + g;
        const size_t r1 = r0 + 8;
        const __half* ph0 = qkvhi + r0 * QKVN + qcol;
        const __half* ph1 = qkvhi + r1 * QKVN + qcol;
        const __half* pl0 = qkvlo + r0 * QKVN + qcol;
        const __half* pl1 = qkvlo + r1 * QKVN + qcol;
#pragma unroll
        for (int ks = 0; ks < 4; ks++) {
            int c0 = t2 + ks * 16;
            qh[ks][0] = *(const uint32_t*)(ph0 + c0);
            qh[ks][1] = *(const uint32_t*)(ph1 + c0);
            qh[ks][2] = *(const uint32_t*)(ph0 + c0 + 8);
            qh[ks][3] = *(const uint32_t*)(ph1 + c0 + 8);
            ql[ks][0] = *(const uint32_t*)(pl0 + c0);
            ql[ks][1] = *(const uint32_t*)(pl1 + c0);
            ql[ks][2] = *(const uint32_t*)(pl0 + c0 + 8);
            ql[ks][3] = *(const uint32_t*)(pl1 + c0 + 8);
        }
    }

    float o[8][4];
#pragma unroll
    for (int nd = 0; nd < 8; nd++)
#pragma unroll
        for (int c = 0; c < 4; c++) o[nd][c] = 0.0f;
    float m0 = -CUDART_INF_F, m1 = -CUDART_INF_F;
    float l0 = 0.0f, l1 = 0.0f;

    for (int kt = 0; kt <= qt; kt++) {
        const int s = kt & 1;
        if (kt + 1 <= qt) {
            load_stage(kt + 1, s ^ 1);
            CP_WAIT(1);
        } else {
            CP_WAIT(0);
        }
        __syncthreads();

        const uint32_t khiS = stgS + s * FT_STAGE;
        const uint32_t vhiS = khiS + FT_TILE;

        // ---- S = Q K^T (2-term) ----
        float sc[16][4];
#pragma unroll
        for (int nf = 0; nf < 16; nf++)
#pragma unroll
            for (int c = 0; c < 4; c++) sc[nf][c] = 0.0f;

#pragma unroll
        for (int ks = 0; ks < 4; ks++) {
            const int kb = ks * 32 + lc16;
#pragma unroll
            for (int kg = 0; kg < 2; kg++) {
                uint32_t tk[4][4];
#pragma unroll
                for (int j = 0; j < 4; j++) {
                    int kf = kg * 4 + j;
                    ldm_x4(tk[j], swz(khiS, kf * 16 + lrow, kb));
                }
#pragma unroll
                for (int j = 0; j < 4; j++) {
                    int kf = kg * 4 + j;
                    uint32_t b0[2] = {tk[j][0], tk[j][2]};
                    uint32_t b1[2] = {tk[j][1], tk[j][3]};
                    mma16816(sc[2 * kf],     qh[ks], b0);
                    mma16816(sc[2 * kf + 1], qh[ks], b1);
                }
#pragma unroll
                for (int j = 0; j < 4; j++) {
                    int kf = kg * 4 + j;
                    uint32_t b0[2] = {tk[j][0], tk[j][2]};
                    uint32_t b1[2] = {tk[j][1], tk[j][3]};
                    mma16816(sc[2 * kf],     ql[ks], b0);
                    mma16816(sc[2 * kf + 1], ql[ks], b1);
                }
            }
        }

        // ---- scale + causal mask + online softmax ----
        const float scale = 0.125f;
        const int rl0 = wid * 16 + g;
        const int rl1 = rl0 + 8;
        float rm0 = -CUDART_INF_F, rm1 = -CUDART_INF_F;
#pragma unroll
        for (int nf = 0; nf < 16; nf++) {
            float c0 = sc[nf][0] * scale, c1 = sc[nf][1] * scale;
            float c2 = sc[nf][2] * scale, c3 = sc[nf][3] * scale;
            if (kt == qt) {
                int col = nf * 8 + t2;
                if (col     > rl0) c0 = -1e30f;
                if (col + 1 > rl0) c1 = -1e30f;
                if (col     > rl1) c2 = -1e30f;
                if (col + 1 > rl1) c3 = -1e30f;
            }
            sc[nf][0] = c0; sc[nf][1] = c1; sc[nf][2] = c2; sc[nf][3] = c3;
            rm0 = fmaxf(rm0, fmaxf(c0, c1));
            rm1 = fmaxf(rm1, fmaxf(c2, c3));
        }
        rm0 = fmaxf(rm0, __shfl_xor_sync(0xffffffffu, rm0, 1));
        rm0 = fmaxf(rm0, __shfl_xor_sync(0xffffffffu, rm0, 2));
        rm1 = fmaxf(rm1, __shfl_xor_sync(0xffffffffu, rm1, 1));
        rm1 = fmaxf(rm1, __shfl_xor_sync(0xffffffffu, rm1, 2));

        const float mn0 = fmaxf(m0, rm0), mn1 = fmaxf(m1, rm1);
        const float a0 = __expf(m0 - mn0), a1 = __expf(m1 - mn1);
        float rs0 = 0.0f, rs1 = 0.0f;
#pragma unroll
        for (int nf = 0; nf < 16; nf++) {
            float p0 = __expf(sc[nf][0] - mn0);
            float p1 = __expf(sc[nf][1] - mn0);
            float p2 = __expf(sc[nf][2] - mn1);
            float p3 = __expf(sc[nf][3] - mn1);
            sc[nf][0] = p0; sc[nf][1] = p1; sc[nf][2] = p2; sc[nf][3] = p3;
            rs0 += p0 + p1;
            rs1 += p2 + p3;
        }
        rs0 += __shfl_xor_sync(0xffffffffu, rs0, 1);
        rs0 += __shfl_xor_sync(0xffffffffu, rs0, 2);
        rs1 += __shfl_xor_sync(0xffffffffu, rs1, 1);
        rs1 += __shfl_xor_sync(0xffffffffu, rs1, 2);
        l0 = l0 * a0 + rs0;
        l1 = l1 * a1 + rs1;
        m0 = mn0;
        m1 = mn1;
#pragma unroll
        for (int nd = 0; nd < 8; nd++) {
            o[nd][0] *= a0; o[nd][1] *= a0;
            o[nd][2] *= a1; o[nd][3] *= a1;
        }

        // ---- O += P V (2-term: (phi+plo) . vhi) ----
#pragma unroll
        for (int kk = 0; kk < 8; kk++) {
            float* p0 = sc[2 * kk];
            float* p1 = sc[2 * kk + 1];
            uint32_t phi[4], plo[4];
            phi[0] = pack_h2(p0[0], p0[1]);
            phi[1] = pack_h2(p0[2], p0[3]);
            phi[2] = pack_h2(p1[0], p1[1]);
            phi[3] = pack_h2(p1[2], p1[3]);
            plo[0] = pack_h2(h_res(p0[0]), h_res(p0[1]));
            plo[1] = pack_h2(h_res(p0[2]), h_res(p0[3]));
            plo[2] = pack_h2(h_res(p1[0]), h_res(p1[1]));
            plo[3] = pack_h2(h_res(p1[2]), h_res(p1[3]));

            uint32_t tv[4][4];
#pragma unroll
            for (int df = 0; df < 4; df++) {
                const int db = df * 32 + lc16;
                ldm_x4_t(tv[df], swz(vhiS, kk * 16 + lrow, db));
            }
#pragma unroll
            for (int df = 0; df < 4; df++) {
                uint32_t v0[2] = {tv[df][0], tv[df][1]};
                uint32_t v1[2] = {tv[df][2], tv[df][3]};
                mma16816(o[2 * df],     phi, v0);
                mma16816(o[2 * df + 1], phi, v1);
            }
#pragma unroll
            for (int df = 0; df < 4; df++) {
                uint32_t v0[2] = {tv[df][0], tv[df][1]};
                uint32_t v1[2] = {tv[df][2], tv[df][3]};
                mma16816(o[2 * df],     plo, v0);
                mma16816(o[2 * df + 1], plo, v1);
            }
        }
        __syncthreads();   // all warps done with stage s before overwrite
    }

    // ---- epilogue: normalize, split to fp16 hi/lo ----
    const float inv0 = 1.0f / l0;
    const float inv1 = 1.0f / l1;
    const size_t r0 = rowQ + wid * 16 + g;
    const size_t r1 = r0 + 8;
#pragma unroll
    for (int nd = 0; nd < 8; nd++) {
        int col = h * DD + nd * 8 + t2;
        float v0 = o[nd][0] * inv0, v1 = o[nd][1] * inv0;
        float v2 = o[nd][2] * inv1, v3 = o[nd][3] * inv1;
        size_t i0 = (r0 * CC + col) >> 1;
        size_t i1 = (r1 * CC + col) >> 1;
        ((uint32_t*)ohi)[i0] = pack_h2(v0, v1);
        ((uint32_t*)olo)[i0] = pack_h2(h_res(v0), h_res(v1));
        ((uint32_t*)ohi)[i1] = pack_h2(v2, v3);
        ((uint32_t*)olo)[i1] = pack_h2(h_res(v2), h_res(v3));
    }
}

// ---------------------------------------------------------------------------
// Launch
// ---------------------------------------------------------------------------
extern "C" void kernel_launch(void* const* d_in, const int* in_sizes, int n_in,
                              void* d_out, int out_size)
{
    (void)in_sizes; (void)n_in; (void)out_size;
    const float* x      = (const float*)d_in[0];
    const float* w_attn = (const float*)d_in[1];
    const float* b_attn = (const float*)d_in[2];
    const float* w_proj = (const float*)d_in[3];
    const float* b_proj = (const float*)d_in[4];
    float* out = (float*)d_out;

    __half *xhi, *xlo, *wahi, *wphi;
    __half *qkvhi, *qkvlo, *ahi, *alo;
    cudaGetSymbolAddress((void**)&xhi,   g_xhi);
    cudaGetSymbolAddress((void**)&xlo,   g_xlo);
    cudaGetSymbolAddress((void**)&wahi,  g_wahi);
    cudaGetSymbolAddress((void**)&wphi,  g_wphi);
    cudaGetSymbolAddress((void**)&qkvhi, g_qkvhi);
    cudaGetSymbolAddress((void**)&qkvlo, g_qkvlo);
    cudaGetSymbolAddress((void**)&ahi,   g_ahi);
    cudaGetSymbolAddress((void**)&alo,   g_alo);

    cudaFuncSetAttribute(gemm_mma_kernel,
                         cudaFuncAttributeMaxDynamicSharedMemorySize, GEMM_SMEM);
    cudaFuncSetAttribute(flash_mma_kernel,
                         cudaFuncAttributeMaxDynamicSharedMemorySize, FLASH_SMEM);

    // 1) fused preprocessing: split x + transpose both weights
    preprocess_kernel<<<PRE_BLKS, 256>>>(x, xhi, xlo, w_attn, wahi, w_proj, wphi);

    // 2) QKV GEMM -> split fp16 hi/lo qkv.
    //    Q columns [0, CC): 2-term A. K/V columns [CC, 3CC): 1-term (hi only) —
    //    flash consumes only the fp16 hi of K/V, so the lo-pass there is wasted work.
    {
        dim3 grid(QKVN / 128, NTOK / 128);
        gemm_mma_kernel<<<grid, 256, GEMM_SMEM>>>(xhi, xlo, wahi,
                                                  b_attn, nullptr, qkvhi, qkvlo,
                                                  NTOK, QKVN, CC, CC);
    }
    // 3) tensor-core flash attention -> split fp16 hi/lo y
    {
        dim3 grid(TT / 128, BB * HH);
        flash_mma_kernel<<<grid, 256, FLASH_SMEM>>>(qkvhi, qkvlo, ahi, alo);
    }
    // 4) proj GEMM -> fp32 out (full 2-term)
    {
        dim3 grid(CC / 128, NTOK / 128);
        gemm_mma_kernel<<<grid, 256, GEMM_SMEM>>>(ahi, alo, wphi,
                                                  b_proj, out, nullptr, nullptr,
                                                  NTOK, CC, CC, CC);
    }
}